// round 1
// baseline (speedup 1.0000x reference)
#include <cuda_runtime.h>
#include <cuda_bf16.h>
#include <cstdint>

// ---------------------------------------------------------------------------
// ManifoldWorms: fp32 baseline pipeline
//   inputs:
//     0 state       (8192,1024) f32
//     1 input_tails (8192, 128) f32
//     2 exit_heads  ( 512, 128) f32
//     3 unit_heads  (  64, 128) f32
//     4 unit_tails  (  64, 128) f32   (UNUSED by reference)
//     5 unit_W      (64,1024,1024) f32
//     6 unit_b      (64,1024) f32
//   output (flat f32):
//     [0      , 524288): exit_outputs (512,1024)
//     [524288 , 525312): garbage      (1024,)
//     [525312 , 590848): units_out    (64,1024)
// ---------------------------------------------------------------------------

#define N_Q     576           // 64 unit + 512 exit queries
#define N_I     8192
#define N_E     128
#define N_C     1024
#define N_U     64
#define N_O     512

// scratch (device globals -- no allocation allowed)
__device__ float g_qn[N_Q * N_E];        // normalized queries
__device__ float g_tinv[N_I];            // 1/||tail_j||
__device__ float g_infl[N_Q * N_I];      // influences (18.9 MB)
__device__ float g_w[N_I];               // 1 - colsum(influences)
__device__ float g_unit_in[N_U * N_C];   // distributed[:64]
__device__ float g_gpart[128 * N_C];     // garbage partials

// ---------------------------------------------------------------------------
// K1: normalize query rows (concat(unit_heads, exit_heads))
// ---------------------------------------------------------------------------
__global__ void k_norm_queries(const float* __restrict__ unit_heads,
                               const float* __restrict__ exit_heads) {
    int row = blockIdx.x;                 // 0..575
    const float* src = (row < N_U) ? (unit_heads + row * N_E)
                                   : (exit_heads + (row - N_U) * N_E);
    float v = src[threadIdx.x];
    float s = v * v;
    #pragma unroll
    for (int o = 16; o; o >>= 1) s += __shfl_xor_sync(0xffffffffu, s, o);
    __shared__ float ws[4];
    if ((threadIdx.x & 31) == 0) ws[threadIdx.x >> 5] = s;
    __syncthreads();
    float tot = ws[0] + ws[1] + ws[2] + ws[3];
    g_qn[row * N_E + threadIdx.x] = v * rsqrtf(tot);
}

// ---------------------------------------------------------------------------
// K2: inverse norms of input_tails rows (one warp per row)
// ---------------------------------------------------------------------------
__global__ void k_tinv(const float* __restrict__ tails) {
    int warp = threadIdx.x >> 5, lane = threadIdx.x & 31;
    int row = blockIdx.x * 4 + warp;
    const float* r = tails + row * N_E;
    float s = 0.f;
    #pragma unroll
    for (int i = 0; i < 4; i++) { float v = r[lane + 32 * i]; s += v * v; }
    #pragma unroll
    for (int o = 16; o; o >>= 1) s += __shfl_xor_sync(0xffffffffu, s, o);
    if (lane == 0) g_tinv[row] = rsqrtf(s);
}

// ---------------------------------------------------------------------------
// K3: sims GEMM + relu -> influences.  M=576(q) N=8192(j) K=128
//     64x64 block tile, 4x4 micro-tile, BK=32
// ---------------------------------------------------------------------------
#define BM 64
#define BN 64
#define BK 32

__global__ void k_sims(const float* __restrict__ tails) {
    __shared__ float As[BK][BM + 1];
    __shared__ float Bs[BK][BN + 1];
    int q0 = blockIdx.x * BM, j0 = blockIdx.y * BN;
    int tid = threadIdx.x;
    int tx = tid & 15, ty = tid >> 4;
    float acc[4][4] = {};

    for (int k0 = 0; k0 < N_E; k0 += BK) {
        #pragma unroll
        for (int i = 0; i < 8; i++) {
            int idx = tid + i * 256;
            int m = idx >> 5, kk = idx & 31;
            As[kk][m] = g_qn[(q0 + m) * N_E + k0 + kk];
            Bs[kk][m] = tails[(j0 + m) * N_E + k0 + kk];
        }
        __syncthreads();
        #pragma unroll
        for (int kk = 0; kk < BK; kk++) {
            float a[4], b[4];
            #pragma unroll
            for (int i = 0; i < 4; i++) a[i] = As[kk][ty + 16 * i];
            #pragma unroll
            for (int j = 0; j < 4; j++) b[j] = Bs[kk][tx + 16 * j];
            #pragma unroll
            for (int i = 0; i < 4; i++)
                #pragma unroll
                for (int j = 0; j < 4; j++) acc[i][j] += a[i] * b[j];
        }
        __syncthreads();
    }
    #pragma unroll
    for (int j = 0; j < 4; j++) {
        int jj = j0 + tx + 16 * j;
        float ti = g_tinv[jj];
        #pragma unroll
        for (int i = 0; i < 4; i++) {
            int q = q0 + ty + 16 * i;
            float v = acc[i][j] * ti;
            g_infl[q * N_I + jj] = v > 0.f ? v : 0.f;
        }
    }
}

// ---------------------------------------------------------------------------
// K4: w[j] = 1 - sum_q influences[q][j]
// ---------------------------------------------------------------------------
__global__ void k_colsum() {
    int j = blockIdx.x * 256 + threadIdx.x;
    float s0 = 0.f, s1 = 0.f, s2 = 0.f, s3 = 0.f;
    for (int q = 0; q < N_Q; q += 4) {
        s0 += g_infl[(q + 0) * N_I + j];
        s1 += g_infl[(q + 1) * N_I + j];
        s2 += g_infl[(q + 2) * N_I + j];
        s3 += g_infl[(q + 3) * N_I + j];
    }
    g_w[j] = 1.0f - (s0 + s1 + s2 + s3);
}

// ---------------------------------------------------------------------------
// K5: distributed = influences @ state.  M=576 N=1024 K=8192
//     rows <64 -> g_unit_in, rows >=64 -> exit_outputs (d_out)
// ---------------------------------------------------------------------------
__global__ void k_dist(const float* __restrict__ state,
                       float* __restrict__ out_exit) {
    __shared__ float As[BK][BM + 1];
    __shared__ float Bs[BK][BN + 1];
    int q0 = blockIdx.x * BM, c0 = blockIdx.y * BN;
    int tid = threadIdx.x;
    int tx = tid & 15, ty = tid >> 4;
    float acc[4][4] = {};

    for (int k0 = 0; k0 < N_I; k0 += BK) {
        #pragma unroll
        for (int i = 0; i < 8; i++) {
            int idx = tid + i * 256;
            int m = idx >> 5, kk = idx & 31;
            As[kk][m] = g_infl[(q0 + m) * N_I + k0 + kk];
        }
        #pragma unroll
        for (int i = 0; i < 8; i++) {
            int idx = tid + i * 256;
            int kk = idx >> 6, cc = idx & 63;
            Bs[kk][cc] = state[(k0 + kk) * N_C + c0 + cc];
        }
        __syncthreads();
        #pragma unroll
        for (int kk = 0; kk < BK; kk++) {
            float a[4], b[4];
            #pragma unroll
            for (int i = 0; i < 4; i++) a[i] = As[kk][ty + 16 * i];
            #pragma unroll
            for (int j = 0; j < 4; j++) b[j] = Bs[kk][tx + 16 * j];
            #pragma unroll
            for (int i = 0; i < 4; i++)
                #pragma unroll
                for (int j = 0; j < 4; j++) acc[i][j] += a[i] * b[j];
        }
        __syncthreads();
    }
    #pragma unroll
    for (int i = 0; i < 4; i++) {
        int q = q0 + ty + 16 * i;
        #pragma unroll
        for (int j = 0; j < 4; j++) {
            int c = c0 + tx + 16 * j;
            float v = acc[i][j];
            if (q < N_U) g_unit_in[q * N_C + c] = v;
            else         out_exit[(q - N_U) * N_C + c] = v;
        }
    }
}

// ---------------------------------------------------------------------------
// K6: garbage partials: part[jc][c] = sum_{j in chunk} w[j]*state[j][c]
//     128 chunks of 64 rows
// ---------------------------------------------------------------------------
__global__ void k_gpart(const float* __restrict__ state) {
    int jc = blockIdx.x;
    int tid = threadIdx.x;   // 256
    float acc[4] = {};
    for (int r = 0; r < 64; r++) {
        int j = jc * 64 + r;
        float wj = g_w[j];
        const float* row = state + (size_t)j * N_C;
        #pragma unroll
        for (int i = 0; i < 4; i++) acc[i] += wj * row[tid + 256 * i];
    }
    #pragma unroll
    for (int i = 0; i < 4; i++) g_gpart[jc * N_C + tid + 256 * i] = acc[i];
}

__global__ void k_greduce(float* __restrict__ out_g) {
    int c = blockIdx.x * 256 + threadIdx.x;
    float s = 0.f;
    for (int p = 0; p < 128; p++) s += g_gpart[p * N_C + c];
    out_g[c] = s;
}

// ---------------------------------------------------------------------------
// K7: units_out[u][d] = in[u][d] + relu( sum_c in[u][c]*W[u][c][d] + b[u][d] )
//     grid (64 units x 4 d-chunks of 256), memory-bound over unit_W (256 MB)
// ---------------------------------------------------------------------------
__global__ void k_units(const float* __restrict__ W,
                        const float* __restrict__ bias,
                        float* __restrict__ out_units) {
    int u = blockIdx.x;
    int d = blockIdx.y * 256 + threadIdx.x;
    __shared__ float sin[N_C];
    for (int i = threadIdx.x; i < N_C; i += 256) sin[i] = g_unit_in[u * N_C + i];
    __syncthreads();
    const float* Wu = W + (size_t)u * N_C * N_C + d;
    float acc = 0.f;
    #pragma unroll 8
    for (int c = 0; c < N_C; c++) acc += sin[c] * Wu[(size_t)c * N_C];
    float h = acc + bias[u * N_C + d];
    out_units[u * N_C + d] = sin[d] + (h > 0.f ? h : 0.f);
}

// ---------------------------------------------------------------------------
extern "C" void kernel_launch(void* const* d_in, const int* in_sizes, int n_in,
                              void* d_out, int out_size) {
    const float* state       = (const float*)d_in[0];
    const float* input_tails = (const float*)d_in[1];
    const float* exit_heads  = (const float*)d_in[2];
    const float* unit_heads  = (const float*)d_in[3];
    // d_in[4] = unit_tails (unused by reference)
    const float* unit_W      = (const float*)d_in[5];
    const float* unit_b      = (const float*)d_in[6];

    float* out = (float*)d_out;
    float* out_exit  = out;                       // 512*1024
    float* out_garb  = out + N_O * N_C;           // 1024
    float* out_units = out + N_O * N_C + N_C;     // 64*1024

    k_norm_queries<<<N_Q, 128>>>(unit_heads, exit_heads);
    k_tinv<<<N_I / 4, 128>>>(input_tails);
    k_sims<<<dim3(N_Q / BM, N_I / BN), 256>>>(input_tails);
    k_colsum<<<N_I / 256, 256>>>();
    k_dist<<<dim3(N_Q / BM, N_C / BN), 256>>>(state, out_exit);
    k_gpart<<<128, 256>>>(state);
    k_greduce<<<N_C / 256, 256>>>(out_garb);
    k_units<<<dim3(N_U, N_C / 256), 256>>>(unit_W, unit_b, out_units);
}

// round 3
// speedup vs baseline: 1.3495x; 1.3495x over previous
#include <cuda_runtime.h>
#include <cuda_bf16.h>
#include <cstdint>

// ---------------------------------------------------------------------------
// ManifoldWorms pipeline, round 3: mma.sync (HMMA) bf16-split GEMM
// (ptxas target is plain sm_100 -> no tcgen05; mma.sync is supported)
//   inputs:
//     0 state       (8192,1024) f32
//     1 input_tails (8192, 128) f32
//     2 exit_heads  ( 512, 128) f32
//     3 unit_heads  (  64, 128) f32
//     4 unit_tails  (  64, 128) f32   (unused)
//     5 unit_W      (64,1024,1024) f32
//     6 unit_b      (64,1024) f32
//   output flat f32: exit_outputs(512x1024) | garbage(1024) | units_out(64x1024)
// ---------------------------------------------------------------------------

#define N_Q   576
#define N_QP  640
#define N_I   8192
#define N_E   128
#define N_C   1024
#define N_U   64
#define N_O   512
#define KSPLIT 4

// ------------------------- device scratch ----------------------------------
__device__ float          g_qn[N_Q * N_E];
__device__ float          g_tinv[N_I];
__device__ __nv_bfloat16  g_Ahi[N_QP * N_I];
__device__ __nv_bfloat16  g_Alo[N_QP * N_I];
__device__ __nv_bfloat16  g_Bhi[N_C * N_I];
__device__ __nv_bfloat16  g_Blo[N_C * N_I];
__device__ float          g_cs[8 * N_I];
__device__ float          g_w[N_I];
__device__ float          g_unit_in[N_U * N_C];
__device__ float          g_gpart[256 * N_C];
__device__ float          g_part[KSPLIT * N_QP * N_C];   // 10.5 MB GEMM partials

// ------------------------- helpers -----------------------------------------
__device__ __forceinline__ uint32_t smem_u32(const void* p) {
    uint32_t a;
    asm("{ .reg .u64 t; cvta.to.shared.u64 t, %1; cvt.u32.u64 %0, t; }"
        : "=r"(a) : "l"(p));
    return a;
}
__device__ __forceinline__ void cp16(uint32_t dst, const void* src) {
    asm volatile("cp.async.cg.shared.global [%0], [%1], 16;\n"
                 :: "r"(dst), "l"(src) : "memory");
}
#define CP_COMMIT() asm volatile("cp.async.commit_group;\n" ::: "memory")
#define CP_WAIT(n)  asm volatile("cp.async.wait_group %0;\n" :: "n"(n) : "memory")

__device__ __forceinline__ void mma_bf16(float* c, const uint32_t* a,
                                         const uint32_t* b) {
    asm volatile(
        "mma.sync.aligned.m16n8k16.row.col.f32.bf16.bf16.f32 "
        "{%0,%1,%2,%3}, {%4,%5,%6,%7}, {%8,%9}, {%0,%1,%2,%3};\n"
        : "+f"(c[0]), "+f"(c[1]), "+f"(c[2]), "+f"(c[3])
        : "r"(a[0]), "r"(a[1]), "r"(a[2]), "r"(a[3]), "r"(b[0]), "r"(b[1]));
}

// ---------------------------------------------------------------------------
// K1: normalize query rows
// ---------------------------------------------------------------------------
__global__ void k_norm_queries(const float* __restrict__ unit_heads,
                               const float* __restrict__ exit_heads) {
    int row = blockIdx.x;
    const float* src = (row < N_U) ? (unit_heads + row * N_E)
                                   : (exit_heads + (row - N_U) * N_E);
    float v = src[threadIdx.x];
    float s = v * v;
    #pragma unroll
    for (int o = 16; o; o >>= 1) s += __shfl_xor_sync(0xffffffffu, s, o);
    __shared__ float ws[4];
    if ((threadIdx.x & 31) == 0) ws[threadIdx.x >> 5] = s;
    __syncthreads();
    float tot = ws[0] + ws[1] + ws[2] + ws[3];
    g_qn[row * N_E + threadIdx.x] = v * rsqrtf(tot);
}

// ---------------------------------------------------------------------------
// K2: inverse norms of input_tails rows
// ---------------------------------------------------------------------------
__global__ void k_tinv(const float* __restrict__ tails) {
    int warp = threadIdx.x >> 5, lane = threadIdx.x & 31;
    int row = blockIdx.x * 4 + warp;
    const float* r = tails + row * N_E;
    float s = 0.f;
    #pragma unroll
    for (int i = 0; i < 4; i++) { float v = r[lane + 32 * i]; s += v * v; }
    #pragma unroll
    for (int o = 16; o; o >>= 1) s += __shfl_xor_sync(0xffffffffu, s, o);
    if (lane == 0) g_tinv[row] = rsqrtf(s);
}

// ---------------------------------------------------------------------------
// K3: sims GEMM + relu -> influences (bf16 hi/lo).  M=576 N=8192 K=128
// ---------------------------------------------------------------------------
#define BM 64
#define BN 64
#define BK 32

__global__ void k_sims(const float* __restrict__ tails) {
    __shared__ float As[BK][BM + 1];
    __shared__ float Bs[BK][BN + 1];
    int q0 = blockIdx.x * BM, j0 = blockIdx.y * BN;
    int tid = threadIdx.x;
    int tx = tid & 15, ty = tid >> 4;
    float acc[4][4] = {};

    for (int k0 = 0; k0 < N_E; k0 += BK) {
        #pragma unroll
        for (int i = 0; i < 8; i++) {
            int idx = tid + i * 256;
            int m = idx >> 5, kk = idx & 31;
            As[kk][m] = g_qn[(q0 + m) * N_E + k0 + kk];
            Bs[kk][m] = tails[(j0 + m) * N_E + k0 + kk];
        }
        __syncthreads();
        #pragma unroll
        for (int kk = 0; kk < BK; kk++) {
            float a[4], b[4];
            #pragma unroll
            for (int i = 0; i < 4; i++) a[i] = As[kk][ty + 16 * i];
            #pragma unroll
            for (int j = 0; j < 4; j++) b[j] = Bs[kk][tx + 16 * j];
            #pragma unroll
            for (int i = 0; i < 4; i++)
                #pragma unroll
                for (int j = 0; j < 4; j++) acc[i][j] += a[i] * b[j];
        }
        __syncthreads();
    }
    #pragma unroll
    for (int j = 0; j < 4; j++) {
        int jj = j0 + tx + 16 * j;
        float ti = g_tinv[jj];
        #pragma unroll
        for (int i = 0; i < 4; i++) {
            int q = q0 + ty + 16 * i;
            float v = acc[i][j] * ti;
            v = v > 0.f ? v : 0.f;
            __nv_bfloat16 hi = __float2bfloat16(v);
            float lo = v - __bfloat162float(hi);
            g_Ahi[q * N_I + jj] = hi;
            g_Alo[q * N_I + jj] = __float2bfloat16(lo);
        }
    }
}

__global__ void k_zeropad() {
    int row = N_Q + blockIdx.x;
    for (int i = threadIdx.x; i < N_I; i += 256) {
        g_Ahi[row * N_I + i] = __float2bfloat16(0.f);
        g_Alo[row * N_I + i] = __float2bfloat16(0.f);
    }
}

// ---------------------------------------------------------------------------
// K4: transpose+split state -> Bhi/Blo [C][K] bf16
// ---------------------------------------------------------------------------
__global__ void k_tsplit(const float* __restrict__ state) {
    __shared__ float t[32][33];
    int k0 = blockIdx.x * 32;
    int c0 = blockIdx.y * 32;
    int tx = threadIdx.x, ty = threadIdx.y;
    #pragma unroll
    for (int i = 0; i < 4; i++)
        t[ty + 8 * i][tx] = state[(size_t)(k0 + ty + 8 * i) * N_C + c0 + tx];
    __syncthreads();
    #pragma unroll
    for (int i = 0; i < 4; i++) {
        int c = c0 + ty + 8 * i;
        int k = k0 + tx;
        float v = t[tx][ty + 8 * i];
        __nv_bfloat16 hi = __float2bfloat16(v);
        float lo = v - __bfloat162float(hi);
        g_Bhi[c * N_I + k] = hi;
        g_Blo[c * N_I + k] = __float2bfloat16(lo);
    }
}

// ---------------------------------------------------------------------------
// K5: colsum partials over q chunks, then w
// ---------------------------------------------------------------------------
__global__ void k_colsum_part() {
    int j = blockIdx.x * 256 + threadIdx.x;
    int qc = blockIdx.y;
    float s = 0.f;
    for (int q = qc * 72; q < (qc + 1) * 72; q++)
        s += __bfloat162float(g_Ahi[q * N_I + j]) +
             __bfloat162float(g_Alo[q * N_I + j]);
    g_cs[qc * N_I + j] = s;
}
__global__ void k_wfinal() {
    int j = blockIdx.x * 256 + threadIdx.x;
    float s = 0.f;
    #pragma unroll
    for (int p = 0; p < 8; p++) s += g_cs[p * N_I + j];
    g_w[j] = 1.0f - s;
}

// ---------------------------------------------------------------------------
// K6: distributed = influences @ state via mma.sync bf16 split, K-split 4
//     CTA tile 64x64, 8 warps (2x4), warp tile 32x16, BK=64, double buffer
// ---------------------------------------------------------------------------
#define KC      64
#define RSTRIDE 36                     // u32 words per smem row (144 B)
#define MATB    (64 * 144)             // 9216 B per matrix tile
#define STAGEB  (4 * MATB)             // 36864 B per stage
#define SMEM_DIST (2 * STAGEB)         // 73728 B

__global__ void __launch_bounds__(256, 2)
k_dist_mma() {
    extern __shared__ uint16_t sh[];
    uint32_t sbase = smem_u32(sh);
    uint32_t* shw = (uint32_t*)sh;

    int tid  = threadIdx.x;
    int wid  = tid >> 5, lane = tid & 31;
    int wm   = wid >> 2, wn = wid & 3;        // warp grid 2 x 4
    int g    = lane >> 2, c = lane & 3;

    int q0 = blockIdx.x * 64;
    int c0 = blockIdx.y * 64;
    int ks = blockIdx.z;
    int kbase = ks * (N_I / KSPLIT);          // 2048-wide K range

    const char* Ah = (const char*)g_Ahi;
    const char* Al = (const char*)g_Alo;
    const char* Bh = (const char*)g_Bhi;
    const char* Bl = (const char*)g_Blo;

    float acc[2][2][4] = {};

    const int NCHUNK = (N_I / KSPLIT) / KC;   // 32

    // ---- async tile loader: 4 matrices of 64 rows x 128B into stage buf ----
    auto load_chunk = [&](int it) {
        int k0 = kbase + it * KC;
        uint32_t buf = sbase + (it & 1) * STAGEB;
        #pragma unroll
        for (int i = 0; i < 2; i++) {
            int u   = tid + i * 256;
            int row = u >> 3, seg = u & 7;
            uint32_t d  = buf + row * 144 + seg * 16;
            long      aoff = ((long)(q0 + row) * N_I + k0 + seg * 8) << 1;
            long      boff = ((long)(c0 + row) * N_I + k0 + seg * 8) << 1;
            cp16(d,            Ah + aoff);
            cp16(d + MATB,     Al + aoff);
            cp16(d + 2 * MATB, Bh + boff);
            cp16(d + 3 * MATB, Bl + boff);
        }
    };

    load_chunk(0);
    CP_COMMIT();

    for (int it = 0; it < NCHUNK; it++) {
        if (it + 1 < NCHUNK) { load_chunk(it + 1); CP_COMMIT(); CP_WAIT(1); }
        else                 { CP_WAIT(0); }
        __syncthreads();

        uint32_t stage_w = ((it & 1) * STAGEB) >> 2;
        const uint32_t* A0 = shw + stage_w;                 // Ahi
        const uint32_t* A1 = A0 + (MATB >> 2);              // Alo
        const uint32_t* B0 = A0 + (2 * MATB >> 2);          // Bhi
        const uint32_t* B1 = A0 + (3 * MATB >> 2);          // Blo

        #pragma unroll
        for (int prod = 0; prod < 3; prod++) {
            const uint32_t* Am = (prod == 2) ? A1 : A0;
            const uint32_t* Bm = (prod == 1) ? B1 : B0;
            #pragma unroll
            for (int kk = 0; kk < 4; kk++) {
                uint32_t a[2][4], b[2][2];
                #pragma unroll
                for (int mi = 0; mi < 2; mi++) {
                    int r = wm * 32 + mi * 16 + g;
                    a[mi][0] = Am[(r)     * RSTRIDE + kk * 8 + c];
                    a[mi][1] = Am[(r + 8) * RSTRIDE + kk * 8 + c];
                    a[mi][2] = Am[(r)     * RSTRIDE + kk * 8 + c + 4];
                    a[mi][3] = Am[(r + 8) * RSTRIDE + kk * 8 + c + 4];
                }
                #pragma unroll
                for (int ni = 0; ni < 2; ni++) {
                    int r = wn * 16 + ni * 8 + g;
                    b[ni][0] = Bm[r * RSTRIDE + kk * 8 + c];
                    b[ni][1] = Bm[r * RSTRIDE + kk * 8 + c + 4];
                }
                #pragma unroll
                for (int mi = 0; mi < 2; mi++)
                    #pragma unroll
                    for (int ni = 0; ni < 2; ni++)
                        mma_bf16(acc[mi][ni], a[mi], b[ni]);
            }
        }
        __syncthreads();
    }

    // ---- write partial tile ----
    float* part = g_part + (size_t)ks * N_QP * N_C;
    #pragma unroll
    for (int mi = 0; mi < 2; mi++) {
        int m0 = q0 + wm * 32 + mi * 16 + g;
        #pragma unroll
        for (int ni = 0; ni < 2; ni++) {
            int n0 = c0 + wn * 16 + ni * 8 + 2 * c;
            part[(size_t)m0 * N_C + n0]           = acc[mi][ni][0];
            part[(size_t)m0 * N_C + n0 + 1]       = acc[mi][ni][1];
            part[(size_t)(m0 + 8) * N_C + n0]     = acc[mi][ni][2];
            part[(size_t)(m0 + 8) * N_C + n0 + 1] = acc[mi][ni][3];
        }
    }
}

// reduce K-split partials and route to outputs
__global__ void k_dist_red(float* __restrict__ out_exit) {
    int m = blockIdx.x;                     // 0..575
    for (int n = threadIdx.x; n < N_C; n += 256) {
        float s = 0.f;
        #pragma unroll
        for (int ks = 0; ks < KSPLIT; ks++)
            s += g_part[((size_t)ks * N_QP + m) * N_C + n];
        if (m < N_U) g_unit_in[m * N_C + n] = s;
        else         out_exit[(size_t)(m - N_U) * N_C + n] = s;
    }
}

// ---------------------------------------------------------------------------
// K7: garbage = sum_j w[j]*state[j][:]
// ---------------------------------------------------------------------------
__global__ void k_gpart(const float* __restrict__ state) {
    int jc = blockIdx.x;
    int tid = threadIdx.x;
    float acc[4] = {};
    for (int r = 0; r < 32; r++) {
        int j = jc * 32 + r;
        float wj = g_w[j];
        const float* row = state + (size_t)j * N_C;
        #pragma unroll
        for (int i = 0; i < 4; i++) acc[i] += wj * row[tid + 256 * i];
    }
    #pragma unroll
    for (int i = 0; i < 4; i++) g_gpart[jc * N_C + tid + 256 * i] = acc[i];
}
__global__ void k_greduce(float* __restrict__ out_g) {
    int c = blockIdx.x * 256 + threadIdx.x;
    float s = 0.f;
    for (int p = 0; p < 256; p++) s += g_gpart[p * N_C + c];
    out_g[c] = s;
}

// ---------------------------------------------------------------------------
// K8: units_out
// ---------------------------------------------------------------------------
__global__ void k_units(const float* __restrict__ W,
                        const float* __restrict__ bias,
                        float* __restrict__ out_units) {
    int u = blockIdx.x;
    int d = blockIdx.y * 256 + threadIdx.x;
    __shared__ float sin[N_C];
    for (int i = threadIdx.x; i < N_C; i += 256) sin[i] = g_unit_in[u * N_C + i];
    __syncthreads();
    const float* Wu = W + (size_t)u * N_C * N_C + d;
    float acc = 0.f;
    #pragma unroll 16
    for (int c = 0; c < N_C; c++) acc += sin[c] * Wu[(size_t)c * N_C];
    float h = acc + bias[u * N_C + d];
    out_units[u * N_C + d] = sin[d] + (h > 0.f ? h : 0.f);
}

// ---------------------------------------------------------------------------
extern "C" void kernel_launch(void* const* d_in, const int* in_sizes, int n_in,
                              void* d_out, int out_size) {
    const float* state       = (const float*)d_in[0];
    const float* input_tails = (const float*)d_in[1];
    const float* exit_heads  = (const float*)d_in[2];
    const float* unit_heads  = (const float*)d_in[3];
    const float* unit_W      = (const float*)d_in[5];
    const float* unit_b      = (const float*)d_in[6];

    float* out       = (float*)d_out;
    float* out_exit  = out;
    float* out_garb  = out + N_O * N_C;
    float* out_units = out + N_O * N_C + N_C;

    cudaFuncSetAttribute(k_dist_mma,
                         cudaFuncAttributeMaxDynamicSharedMemorySize,
                         SMEM_DIST);

    k_norm_queries<<<N_Q, 128>>>(unit_heads, exit_heads);
    k_tinv<<<N_I / 4, 128>>>(input_tails);
    k_sims<<<dim3(N_Q / BM, N_I / BN), 256>>>(input_tails);
    k_zeropad<<<N_QP - N_Q, 256>>>();
    k_tsplit<<<dim3(N_I / 32, N_C / 32), dim3(32, 8)>>>(state);
    k_colsum_part<<<dim3(N_I / 256, 8), 256>>>();
    k_wfinal<<<N_I / 256, 256>>>();
    k_dist_mma<<<dim3(N_QP / 64, N_C / 64, KSPLIT), 256, SMEM_DIST>>>();
    k_dist_red<<<N_Q, 256>>>(out_exit);
    k_gpart<<<256, 256>>>(state);
    k_greduce<<<N_C / 256, 256>>>(out_garb);
    k_units<<<dim3(N_U, N_C / 256), 256>>>(unit_W, unit_b, out_units);
}

// round 7
// speedup vs baseline: 1.3819x; 1.0240x over previous
#include <cuda_runtime.h>
#include <cuda_bf16.h>
#include <cstdint>

// ---------------------------------------------------------------------------
// ManifoldWorms pipeline, round 6: R3-passing pipeline + ldmatrix k_dist only
//   output flat f32: exit_outputs(512x1024) | garbage(1024) | units_out(64x1024)
// ---------------------------------------------------------------------------

#define N_Q   576
#define N_QP  640
#define N_I   8192
#define N_E   128
#define N_C   1024
#define N_U   64
#define N_O   512
#define KSPLIT 8

// ------------------------- device scratch ----------------------------------
__device__ float          g_qn[N_Q * N_E];
__device__ float          g_tinv[N_I];
__device__ __nv_bfloat16  g_Ahi[N_QP * N_I];
__device__ __nv_bfloat16  g_Alo[N_QP * N_I];
__device__ __nv_bfloat16  g_Bhi[N_C * N_I];
__device__ __nv_bfloat16  g_Blo[N_C * N_I];
__device__ float          g_cs[8 * N_I];
__device__ float          g_w[N_I];
__device__ float          g_unit_in[N_U * N_C];
__device__ float          g_gpart[256 * N_C];
__device__ float          g_part[KSPLIT * N_QP * N_C];   // 21 MB GEMM partials

// ------------------------- helpers -----------------------------------------
__device__ __forceinline__ uint32_t smem_u32(const void* p) {
    uint32_t a;
    asm("{ .reg .u64 t; cvta.to.shared.u64 t, %1; cvt.u32.u64 %0, t; }"
        : "=r"(a) : "l"(p));
    return a;
}
__device__ __forceinline__ void cp16(uint32_t dst, const void* src) {
    asm volatile("cp.async.cg.shared.global [%0], [%1], 16;\n"
                 :: "r"(dst), "l"(src) : "memory");
}
#define CP_COMMIT() asm volatile("cp.async.commit_group;\n" ::: "memory")
#define CP_WAIT(n)  asm volatile("cp.async.wait_group %0;\n" :: "n"(n) : "memory")

__device__ __forceinline__ void ldm_x4(uint32_t* r, uint32_t addr) {
    asm volatile("ldmatrix.sync.aligned.m8n8.x4.shared.b16 {%0,%1,%2,%3}, [%4];"
        : "=r"(r[0]), "=r"(r[1]), "=r"(r[2]), "=r"(r[3]) : "r"(addr));
}
__device__ __forceinline__ void mma_bf16(float* c, const uint32_t* a,
                                         uint32_t b0, uint32_t b1) {
    asm volatile(
        "mma.sync.aligned.m16n8k16.row.col.f32.bf16.bf16.f32 "
        "{%0,%1,%2,%3}, {%4,%5,%6,%7}, {%8,%9}, {%0,%1,%2,%3};\n"
        : "+f"(c[0]), "+f"(c[1]), "+f"(c[2]), "+f"(c[3])
        : "r"(a[0]), "r"(a[1]), "r"(a[2]), "r"(a[3]), "r"(b0), "r"(b1));
}

// ---------------------------------------------------------------------------
// K1: normalize query rows
// ---------------------------------------------------------------------------
__global__ void k_norm_queries(const float* __restrict__ unit_heads,
                               const float* __restrict__ exit_heads) {
    int row = blockIdx.x;
    const float* src = (row < N_U) ? (unit_heads + row * N_E)
                                   : (exit_heads + (row - N_U) * N_E);
    float v = src[threadIdx.x];
    float s = v * v;
    #pragma unroll
    for (int o = 16; o; o >>= 1) s += __shfl_xor_sync(0xffffffffu, s, o);
    __shared__ float ws[4];
    if ((threadIdx.x & 31) == 0) ws[threadIdx.x >> 5] = s;
    __syncthreads();
    float tot = ws[0] + ws[1] + ws[2] + ws[3];
    g_qn[row * N_E + threadIdx.x] = v * rsqrtf(tot);
}

// ---------------------------------------------------------------------------
// K2: inverse norms of input_tails rows
// ---------------------------------------------------------------------------
__global__ void k_tinv(const float* __restrict__ tails) {
    int warp = threadIdx.x >> 5, lane = threadIdx.x & 31;
    int row = blockIdx.x * 4 + warp;
    const float* r = tails + row * N_E;
    float s = 0.f;
    #pragma unroll
    for (int i = 0; i < 4; i++) { float v = r[lane + 32 * i]; s += v * v; }
    #pragma unroll
    for (int o = 16; o; o >>= 1) s += __shfl_xor_sync(0xffffffffu, s, o);
    if (lane == 0) g_tinv[row] = rsqrtf(s);
}

// ---------------------------------------------------------------------------
// K3: sims GEMM + relu -> influences (bf16 hi/lo).  M=576 N=8192 K=128
// ---------------------------------------------------------------------------
#define BM 64
#define BN 64
#define BK 32

__global__ void k_sims(const float* __restrict__ tails) {
    __shared__ float As[BK][BM + 1];
    __shared__ float Bs[BK][BN + 1];
    int q0 = blockIdx.x * BM, j0 = blockIdx.y * BN;
    int tid = threadIdx.x;
    int tx = tid & 15, ty = tid >> 4;
    float acc[4][4] = {};

    for (int k0 = 0; k0 < N_E; k0 += BK) {
        #pragma unroll
        for (int i = 0; i < 8; i++) {
            int idx = tid + i * 256;
            int m = idx >> 5, kk = idx & 31;
            As[kk][m] = g_qn[(q0 + m) * N_E + k0 + kk];
            Bs[kk][m] = tails[(j0 + m) * N_E + k0 + kk];
        }
        __syncthreads();
        #pragma unroll
        for (int kk = 0; kk < BK; kk++) {
            float a[4], b[4];
            #pragma unroll
            for (int i = 0; i < 4; i++) a[i] = As[kk][ty + 16 * i];
            #pragma unroll
            for (int j = 0; j < 4; j++) b[j] = Bs[kk][tx + 16 * j];
            #pragma unroll
            for (int i = 0; i < 4; i++)
                #pragma unroll
                for (int j = 0; j < 4; j++) acc[i][j] += a[i] * b[j];
        }
        __syncthreads();
    }
    #pragma unroll
    for (int j = 0; j < 4; j++) {
        int jj = j0 + tx + 16 * j;
        float ti = g_tinv[jj];
        #pragma unroll
        for (int i = 0; i < 4; i++) {
            int q = q0 + ty + 16 * i;
            float v = acc[i][j] * ti;
            v = v > 0.f ? v : 0.f;
            __nv_bfloat16 hi = __float2bfloat16(v);
            float lo = v - __bfloat162float(hi);
            g_Ahi[q * N_I + jj] = hi;
            g_Alo[q * N_I + jj] = __float2bfloat16(lo);
        }
    }
}

// zero pad rows 576..639 of A  (exact R3-passing version)
__global__ void k_zeropad() {
    int row = N_Q + blockIdx.x;
    for (int i = threadIdx.x; i < N_I; i += 256) {
        g_Ahi[row * N_I + i] = __float2bfloat16(0.f);
        g_Alo[row * N_I + i] = __float2bfloat16(0.f);
    }
}

// ---------------------------------------------------------------------------
// K4: transpose+split state -> Bhi/Blo [C][K] bf16
// ---------------------------------------------------------------------------
__global__ void k_tsplit(const float* __restrict__ state) {
    __shared__ float t[32][33];
    int k0 = blockIdx.x * 32;
    int c0 = blockIdx.y * 32;
    int tx = threadIdx.x, ty = threadIdx.y;
    #pragma unroll
    for (int i = 0; i < 4; i++)
        t[ty + 8 * i][tx] = state[(size_t)(k0 + ty + 8 * i) * N_C + c0 + tx];
    __syncthreads();
    #pragma unroll
    for (int i = 0; i < 4; i++) {
        int c = c0 + ty + 8 * i;
        int k = k0 + tx;
        float v = t[tx][ty + 8 * i];
        __nv_bfloat16 hi = __float2bfloat16(v);
        float lo = v - __bfloat162float(hi);
        g_Bhi[c * N_I + k] = hi;
        g_Blo[c * N_I + k] = __float2bfloat16(lo);
    }
}

// ---------------------------------------------------------------------------
// K5: colsum partials over q chunks, then w
// ---------------------------------------------------------------------------
__global__ void k_colsum_part() {
    int j = blockIdx.x * 256 + threadIdx.x;
    int qc = blockIdx.y;
    float s = 0.f;
    for (int q = qc * 72; q < (qc + 1) * 72; q++)
        s += __bfloat162float(g_Ahi[q * N_I + j]) +
             __bfloat162float(g_Alo[q * N_I + j]);
    g_cs[qc * N_I + j] = s;
}
__global__ void k_wfinal() {
    int j = blockIdx.x * 256 + threadIdx.x;
    float s = 0.f;
    #pragma unroll
    for (int p = 0; p < 8; p++) s += g_cs[p * N_I + j];
    g_w[j] = 1.0f - s;
}

// ---------------------------------------------------------------------------
// K6: distributed = influences @ state; mma.sync bf16 split + ldmatrix
//     CTA 64x64, 8 warps (2x4), warp tile 32x16, BK=64, double buffer
// ---------------------------------------------------------------------------
#define KC      64
#define MATB    (64 * 144)             // 9216 B per matrix tile (144B rows)
#define STAGEB  (4 * MATB)             // 36864 B per stage
#define SMEM_DIST (2 * STAGEB)

__global__ void __launch_bounds__(256, 2)
k_dist_mma() {
    extern __shared__ uint16_t sh[];
    uint32_t sbase = smem_u32(sh);

    int tid  = threadIdx.x;
    int wid  = tid >> 5, lane = tid & 31;
    int wm   = wid >> 2, wn = wid & 3;
    int g    = lane >> 2, c = lane & 3;
    int l15  = lane & 15;
    int lhalf = (lane >> 4) << 4;

    int q0 = blockIdx.x * 64;
    int c0 = blockIdx.y * 64;
    int ks = blockIdx.z;
    int kbase = ks * (N_I / KSPLIT);   // 1024-wide K range

    const char* Ah = (const char*)g_Ahi;
    const char* Al = (const char*)g_Alo;
    const char* Bh = (const char*)g_Bhi;
    const char* Bl = (const char*)g_Blo;

    float acc[2][2][4] = {};
    const int NCHUNK = (N_I / KSPLIT) / KC;   // 16

    auto load_chunk = [&](int it) {
        int k0 = kbase + it * KC;
        uint32_t buf = sbase + (it & 1) * STAGEB;
        #pragma unroll
        for (int i = 0; i < 2; i++) {
            int u   = tid + i * 256;
            int row = u >> 3, seg = u & 7;
            uint32_t d  = buf + row * 144 + seg * 16;
            long aoff = ((long)(q0 + row) * N_I + k0 + seg * 8) << 1;
            long boff = ((long)(c0 + row) * N_I + k0 + seg * 8) << 1;
            cp16(d,            Ah + aoff);
            cp16(d + MATB,     Al + aoff);
            cp16(d + 2 * MATB, Bh + boff);
            cp16(d + 3 * MATB, Bl + boff);
        }
    };

    load_chunk(0);
    CP_COMMIT();

    for (int it = 0; it < NCHUNK; it++) {
        if (it + 1 < NCHUNK) { load_chunk(it + 1); CP_COMMIT(); CP_WAIT(1); }
        else                 { CP_WAIT(0); }
        __syncthreads();

        uint32_t buf = sbase + (it & 1) * STAGEB;
        uint32_t aRow0 = buf + (wm * 32 + l15) * 144 + lhalf;
        uint32_t aRow1 = aRow0 + 16 * 144;
        uint32_t bRow  = buf + 2 * MATB + (wn * 16 + l15) * 144 + lhalf;

        #pragma unroll
        for (int kk = 0; kk < 4; kk++) {
            uint32_t ahi[2][4], alo[2][4], bhi[4], blo[4];
            int cb = kk * 32;
            ldm_x4(ahi[0], aRow0 + cb);
            ldm_x4(ahi[1], aRow1 + cb);
            ldm_x4(alo[0], aRow0 + MATB + cb);
            ldm_x4(alo[1], aRow1 + MATB + cb);
            ldm_x4(bhi,    bRow + cb);
            ldm_x4(blo,    bRow + MATB + cb);
            #pragma unroll
            for (int mi = 0; mi < 2; mi++) {
                mma_bf16(acc[mi][0], ahi[mi], bhi[0], bhi[2]);
                mma_bf16(acc[mi][1], ahi[mi], bhi[1], bhi[3]);
                mma_bf16(acc[mi][0], ahi[mi], blo[0], blo[2]);
                mma_bf16(acc[mi][1], ahi[mi], blo[1], blo[3]);
                mma_bf16(acc[mi][0], alo[mi], bhi[0], bhi[2]);
                mma_bf16(acc[mi][1], alo[mi], bhi[1], bhi[3]);
            }
        }
        __syncthreads();
    }

    float* part = g_part + (size_t)ks * N_QP * N_C;
    #pragma unroll
    for (int mi = 0; mi < 2; mi++) {
        int m0 = q0 + wm * 32 + mi * 16 + g;
        #pragma unroll
        for (int ni = 0; ni < 2; ni++) {
            int n0 = c0 + wn * 16 + ni * 8 + 2 * c;
            part[(size_t)m0 * N_C + n0]           = acc[mi][ni][0];
            part[(size_t)m0 * N_C + n0 + 1]       = acc[mi][ni][1];
            part[(size_t)(m0 + 8) * N_C + n0]     = acc[mi][ni][2];
            part[(size_t)(m0 + 8) * N_C + n0 + 1] = acc[mi][ni][3];
        }
    }
}

__global__ void k_dist_red(float* __restrict__ out_exit) {
    int m = blockIdx.x;
    for (int n = threadIdx.x; n < N_C; n += 256) {
        float s = 0.f;
        #pragma unroll
        for (int ks = 0; ks < KSPLIT; ks++)
            s += g_part[((size_t)ks * N_QP + m) * N_C + n];
        if (m < N_U) g_unit_in[m * N_C + n] = s;
        else         out_exit[(size_t)(m - N_U) * N_C + n] = s;
    }
}

// ---------------------------------------------------------------------------
// K7: garbage = sum_j w[j]*state[j][:]
// ---------------------------------------------------------------------------
__global__ void k_gpart(const float* __restrict__ state) {
    int jc = blockIdx.x;
    int tid = threadIdx.x;
    float acc[4] = {};
    for (int r = 0; r < 32; r++) {
        int j = jc * 32 + r;
        float wj = g_w[j];
        const float* row = state + (size_t)j * N_C;
        #pragma unroll
        for (int i = 0; i < 4; i++) acc[i] += wj * row[tid + 256 * i];
    }
    #pragma unroll
    for (int i = 0; i < 4; i++) g_gpart[jc * N_C + tid + 256 * i] = acc[i];
}
__global__ void k_greduce(float* __restrict__ out_g) {
    int c = blockIdx.x * 256 + threadIdx.x;
    float s = 0.f;
    for (int p = 0; p < 256; p++) s += g_gpart[p * N_C + c];
    out_g[c] = s;
}

// ---------------------------------------------------------------------------
// K8: units_out  (exact R3-passing version)
// ---------------------------------------------------------------------------
__global__ void k_units(const float* __restrict__ W,
                        const float* __restrict__ bias,
                        float* __restrict__ out_units) {
    int u = blockIdx.x;
    int d = blockIdx.y * 256 + threadIdx.x;
    __shared__ float sin[N_C];
    for (int i = threadIdx.x; i < N_C; i += 256) sin[i] = g_unit_in[u * N_C + i];
    __syncthreads();
    const float* Wu = W + (size_t)u * N_C * N_C + d;
    float acc = 0.f;
    #pragma unroll 16
    for (int c = 0; c < N_C; c++) acc += sin[c] * Wu[(size_t)c * N_C];
    float h = acc + bias[u * N_C + d];
    out_units[u * N_C + d] = sin[d] + (h > 0.f ? h : 0.f);
}

// ---------------------------------------------------------------------------
extern "C" void kernel_launch(void* const* d_in, const int* in_sizes, int n_in,
                              void* d_out, int out_size) {
    const float* state       = (const float*)d_in[0];
    const float* input_tails = (const float*)d_in[1];
    const float* exit_heads  = (const float*)d_in[2];
    const float* unit_heads  = (const float*)d_in[3];
    const float* unit_W      = (const float*)d_in[5];
    const float* unit_b      = (const float*)d_in[6];

    float* out       = (float*)d_out;
    float* out_exit  = out;
    float* out_garb  = out + N_O * N_C;
    float* out_units = out + N_O * N_C + N_C;

    cudaFuncSetAttribute(k_dist_mma,
                         cudaFuncAttributeMaxDynamicSharedMemorySize,
                         SMEM_DIST);

    k_norm_queries<<<N_Q, 128>>>(unit_heads, exit_heads);
    k_tinv<<<N_I / 4, 128>>>(input_tails);
    k_sims<<<dim3(N_Q / BM, N_I / BN), 256>>>(input_tails);
    k_zeropad<<<N_QP - N_Q, 256>>>();
    k_tsplit<<<dim3(N_I / 32, N_C / 32), dim3(32, 8)>>>(state);
    k_colsum_part<<<dim3(N_I / 256, 8), 256>>>();
    k_wfinal<<<N_I / 256, 256>>>();
    k_dist_mma<<<dim3(N_QP / 64, N_C / 64, KSPLIT), 256, SMEM_DIST>>>();
    k_dist_red<<<N_Q, 256>>>(out_exit);
    k_gpart<<<256, 256>>>(state);
    k_greduce<<<N_C / 256, 256>>>(out_garb);
    k_units<<<dim3(N_U, N_C / 256), 256>>>(unit_W, unit_b, out_units);
}

// round 9
// speedup vs baseline: 1.5374x; 1.1125x over previous
#include <cuda_runtime.h>
#include <cuda_bf16.h>
#include <cuda_fp16.h>
#include <cstdint>

// ---------------------------------------------------------------------------
// ManifoldWorms pipeline, round 8 (= round 7 resubmit): fp16 2-product split
//   output flat f32: exit_outputs(512x1024) | garbage(1024) | units_out(64x1024)
// ---------------------------------------------------------------------------

#define N_Q   576
#define N_QP  640
#define N_I   8192
#define N_E   128
#define N_C   1024
#define N_U   64
#define N_O   512
#define KSPLIT 8

// ------------------------- device scratch ----------------------------------
__device__ float   g_qn[N_Q * N_E];
__device__ float   g_tinv[N_I];
__device__ __half  g_A [N_QP * N_I];      // influences fp16
__device__ __half  g_B1[N_C * N_I];       // state^T hi fp16
__device__ __half  g_B2[N_C * N_I];       // state^T lo fp16
__device__ float   g_cs[8 * N_I];
__device__ float   g_w[N_I];
__device__ float   g_unit_in[N_U * N_C];
__device__ float   g_gpart[256 * N_C];
__device__ float   g_part[KSPLIT * N_QP * N_C];   // 21 MB GEMM partials

// ------------------------- helpers -----------------------------------------
__device__ __forceinline__ uint32_t smem_u32(const void* p) {
    uint32_t a;
    asm("{ .reg .u64 t; cvta.to.shared.u64 t, %1; cvt.u32.u64 %0, t; }"
        : "=r"(a) : "l"(p));
    return a;
}
__device__ __forceinline__ void cp16(uint32_t dst, const void* src) {
    asm volatile("cp.async.cg.shared.global [%0], [%1], 16;\n"
                 :: "r"(dst), "l"(src) : "memory");
}
#define CP_COMMIT() asm volatile("cp.async.commit_group;\n" ::: "memory")
#define CP_WAIT(n)  asm volatile("cp.async.wait_group %0;\n" :: "n"(n) : "memory")

__device__ __forceinline__ void ldm_x4(uint32_t* r, uint32_t addr) {
    asm volatile("ldmatrix.sync.aligned.m8n8.x4.shared.b16 {%0,%1,%2,%3}, [%4];"
        : "=r"(r[0]), "=r"(r[1]), "=r"(r[2]), "=r"(r[3]) : "r"(addr));
}
__device__ __forceinline__ void mma_f16(float* c, const uint32_t* a,
                                        uint32_t b0, uint32_t b1) {
    asm volatile(
        "mma.sync.aligned.m16n8k16.row.col.f32.f16.f16.f32 "
        "{%0,%1,%2,%3}, {%4,%5,%6,%7}, {%8,%9}, {%0,%1,%2,%3};\n"
        : "+f"(c[0]), "+f"(c[1]), "+f"(c[2]), "+f"(c[3])
        : "r"(a[0]), "r"(a[1]), "r"(a[2]), "r"(a[3]), "r"(b0), "r"(b1));
}

// ---------------------------------------------------------------------------
// K0 (prep1): fused query-normalize + tail inverse norms
// ---------------------------------------------------------------------------
__global__ void k_prep1(const float* __restrict__ unit_heads,
                        const float* __restrict__ exit_heads,
                        const float* __restrict__ tails) {
    if (blockIdx.x < N_Q) {
        int row = blockIdx.x;
        const float* src = (row < N_U) ? (unit_heads + row * N_E)
                                       : (exit_heads + (row - N_U) * N_E);
        float v = src[threadIdx.x];
        float s = v * v;
        #pragma unroll
        for (int o = 16; o; o >>= 1) s += __shfl_xor_sync(0xffffffffu, s, o);
        __shared__ float ws[4];
        if ((threadIdx.x & 31) == 0) ws[threadIdx.x >> 5] = s;
        __syncthreads();
        float tot = ws[0] + ws[1] + ws[2] + ws[3];
        g_qn[row * N_E + threadIdx.x] = v * rsqrtf(tot);
    } else {
        int warp = threadIdx.x >> 5, lane = threadIdx.x & 31;
        int row = (blockIdx.x - N_Q) * 4 + warp;
        const float* r = tails + row * N_E;
        float s = 0.f;
        #pragma unroll
        for (int i = 0; i < 4; i++) { float v = r[lane + 32 * i]; s += v * v; }
        #pragma unroll
        for (int o = 16; o; o >>= 1) s += __shfl_xor_sync(0xffffffffu, s, o);
        if (lane == 0) g_tinv[row] = rsqrtf(s);
    }
}

// ---------------------------------------------------------------------------
// K1 (sims): sims GEMM + relu -> influences fp16.  M=576 N=8192 K=128
// ---------------------------------------------------------------------------
#define BM 64
#define BN 64
#define BK 32

__global__ void k_sims(const float* __restrict__ tails) {
    __shared__ float As[BK][BM + 1];
    __shared__ float Bs[BK][BN + 1];
    int q0 = blockIdx.x * BM, j0 = blockIdx.y * BN;
    int tid = threadIdx.x;
    int tx = tid & 15, ty = tid >> 4;
    float acc[4][4] = {};

    for (int k0 = 0; k0 < N_E; k0 += BK) {
        #pragma unroll
        for (int i = 0; i < 8; i++) {
            int idx = tid + i * 256;
            int m = idx >> 5, kk = idx & 31;
            As[kk][m] = g_qn[(q0 + m) * N_E + k0 + kk];
            Bs[kk][m] = tails[(j0 + m) * N_E + k0 + kk];
        }
        __syncthreads();
        #pragma unroll
        for (int kk = 0; kk < BK; kk++) {
            float a[4], b[4];
            #pragma unroll
            for (int i = 0; i < 4; i++) a[i] = As[kk][ty + 16 * i];
            #pragma unroll
            for (int j = 0; j < 4; j++) b[j] = Bs[kk][tx + 16 * j];
            #pragma unroll
            for (int i = 0; i < 4; i++)
                #pragma unroll
                for (int j = 0; j < 4; j++) acc[i][j] += a[i] * b[j];
        }
        __syncthreads();
    }
    #pragma unroll
    for (int j = 0; j < 4; j++) {
        int jj = j0 + tx + 16 * j;
        float ti = g_tinv[jj];
        #pragma unroll
        for (int i = 0; i < 4; i++) {
            int q = q0 + ty + 16 * i;
            float v = acc[i][j] * ti;
            v = v > 0.f ? v : 0.f;
            g_A[q * N_I + jj] = __float2half(v);
        }
    }
}

// ---------------------------------------------------------------------------
// K2 (prep2): fused state transpose+split (fp16 hi/lo) + A-pad zero
// ---------------------------------------------------------------------------
__global__ void k_prep2(const float* __restrict__ state) {
    if (blockIdx.x < 8192) {
        __shared__ float t[32][33];
        int kb = blockIdx.x & 255;
        int cb = blockIdx.x >> 8;
        int k0 = kb * 32, c0 = cb * 32;
        int tx = threadIdx.x & 31, ty = threadIdx.x >> 5;
        #pragma unroll
        for (int i = 0; i < 4; i++)
            t[ty + 8 * i][tx] = state[(size_t)(k0 + ty + 8 * i) * N_C + c0 + tx];
        __syncthreads();
        #pragma unroll
        for (int i = 0; i < 4; i++) {
            int c = c0 + ty + 8 * i;
            int k = k0 + tx;
            float v = t[tx][ty + 8 * i];
            __half h1 = __float2half(v);
            g_B1[c * N_I + k] = h1;
            g_B2[c * N_I + k] = __float2half(v - __half2float(h1));
        }
    } else {
        int row = N_Q + (blockIdx.x - 8192);
        for (int i = threadIdx.x; i < N_I; i += 256)
            g_A[row * N_I + i] = __float2half(0.f);
    }
}

// ---------------------------------------------------------------------------
// K3 (dist): distributed = influences @ state; fp16 2-product mma.sync
//     CTA 64x64, 8 warps (2x4), BK=64, double buffer, KSPLIT=8
// ---------------------------------------------------------------------------
#define KC      64
#define MATB    (64 * 144)             // 9216 B per matrix tile (144B rows)
#define STAGEB  (3 * MATB)             // 27648 B per stage (A, B1, B2)
#define SMEM_DIST (2 * STAGEB)         // 55296 B

__global__ void __launch_bounds__(256, 2)
k_dist_mma() {
    extern __shared__ uint16_t sh[];
    uint32_t sbase = smem_u32(sh);

    int tid  = threadIdx.x;
    int wid  = tid >> 5, lane = tid & 31;
    int wm   = wid >> 2, wn = wid & 3;
    int g    = lane >> 2, c = lane & 3;
    int l15  = lane & 15;
    int lhalf = (lane >> 4) << 4;

    int q0 = blockIdx.x * 64;
    int c0 = blockIdx.y * 64;
    int ks = blockIdx.z;
    int kbase = ks * (N_I / KSPLIT);

    const char* Aa = (const char*)g_A;
    const char* B1 = (const char*)g_B1;
    const char* B2 = (const char*)g_B2;

    float acc[2][2][4] = {};
    const int NCHUNK = (N_I / KSPLIT) / KC;   // 16

    auto load_chunk = [&](int it) {
        int k0 = kbase + it * KC;
        uint32_t buf = sbase + (it & 1) * STAGEB;
        #pragma unroll
        for (int i = 0; i < 2; i++) {
            int u   = tid + i * 256;
            int row = u >> 3, seg = u & 7;
            uint32_t d  = buf + row * 144 + seg * 16;
            long aoff = ((long)(q0 + row) * N_I + k0 + seg * 8) << 1;
            long boff = ((long)(c0 + row) * N_I + k0 + seg * 8) << 1;
            cp16(d,            Aa + aoff);
            cp16(d + MATB,     B1 + boff);
            cp16(d + 2 * MATB, B2 + boff);
        }
    };

    load_chunk(0);
    CP_COMMIT();

    for (int it = 0; it < NCHUNK; it++) {
        if (it + 1 < NCHUNK) { load_chunk(it + 1); CP_COMMIT(); CP_WAIT(1); }
        else                 { CP_WAIT(0); }
        __syncthreads();

        uint32_t buf = sbase + (it & 1) * STAGEB;
        uint32_t aRow0 = buf + (wm * 32 + l15) * 144 + lhalf;
        uint32_t aRow1 = aRow0 + 16 * 144;
        uint32_t bRow  = buf + MATB + (wn * 16 + l15) * 144 + lhalf;

        #pragma unroll
        for (int kk = 0; kk < 4; kk++) {
            uint32_t a[2][4], b1[4], b2[4];
            int cb = kk * 32;
            ldm_x4(a[0], aRow0 + cb);
            ldm_x4(a[1], aRow1 + cb);
            ldm_x4(b1,   bRow + cb);
            ldm_x4(b2,   bRow + MATB + cb);
            #pragma unroll
            for (int mi = 0; mi < 2; mi++) {
                mma_f16(acc[mi][0], a[mi], b1[0], b1[2]);
                mma_f16(acc[mi][1], a[mi], b1[1], b1[3]);
                mma_f16(acc[mi][0], a[mi], b2[0], b2[2]);
                mma_f16(acc[mi][1], a[mi], b2[1], b2[3]);
            }
        }
        __syncthreads();
    }

    float* part = g_part + (size_t)ks * N_QP * N_C;
    #pragma unroll
    for (int mi = 0; mi < 2; mi++) {
        int m0 = q0 + wm * 32 + mi * 16 + g;
        #pragma unroll
        for (int ni = 0; ni < 2; ni++) {
            int n0 = c0 + wn * 16 + ni * 8 + 2 * c;
            part[(size_t)m0 * N_C + n0]           = acc[mi][ni][0];
            part[(size_t)m0 * N_C + n0 + 1]       = acc[mi][ni][1];
            part[(size_t)(m0 + 8) * N_C + n0]     = acc[mi][ni][2];
            part[(size_t)(m0 + 8) * N_C + n0 + 1] = acc[mi][ni][3];
        }
    }
}

// ---------------------------------------------------------------------------
// K4/K5: colsum partials over q chunks, then w
// ---------------------------------------------------------------------------
__global__ void k_colsum_part() {
    int j = blockIdx.x * 256 + threadIdx.x;
    int qc = blockIdx.y;
    float s = 0.f;
    for (int q = qc * 72; q < (qc + 1) * 72; q++)
        s += __half2float(g_A[q * N_I + j]);
    g_cs[qc * N_I + j] = s;
}
__global__ void k_wfinal() {
    int j = blockIdx.x * 256 + threadIdx.x;
    float s = 0.f;
    #pragma unroll
    for (int p = 0; p < 8; p++) s += g_cs[p * N_I + j];
    g_w[j] = 1.0f - s;
}

// ---------------------------------------------------------------------------
// K6: reduce K-split partials and route to outputs
// ---------------------------------------------------------------------------
__global__ void k_dist_red(float* __restrict__ out_exit) {
    int m = blockIdx.x;
    for (int n = threadIdx.x; n < N_C; n += 256) {
        float s = 0.f;
        #pragma unroll
        for (int ks = 0; ks < KSPLIT; ks++)
            s += g_part[((size_t)ks * N_QP + m) * N_C + n];
        if (m < N_U) g_unit_in[m * N_C + n] = s;
        else         out_exit[(size_t)(m - N_U) * N_C + n] = s;
    }
}

// ---------------------------------------------------------------------------
// K7: garbage = sum_j w[j]*state[j][:]
// ---------------------------------------------------------------------------
__global__ void k_gpart(const float* __restrict__ state) {
    int jc = blockIdx.x;
    int tid = threadIdx.x;
    float acc[4] = {};
    for (int r = 0; r < 32; r++) {
        int j = jc * 32 + r;
        float wj = g_w[j];
        const float* row = state + (size_t)j * N_C;
        #pragma unroll
        for (int i = 0; i < 4; i++) acc[i] += wj * row[tid + 256 * i];
    }
    #pragma unroll
    for (int i = 0; i < 4; i++) g_gpart[jc * N_C + tid + 256 * i] = acc[i];
}
__global__ void k_greduce(float* __restrict__ out_g) {
    int c = blockIdx.x * 256 + threadIdx.x;
    float s = 0.f;
    for (int p = 0; p < 256; p++) s += g_gpart[p * N_C + c];
    out_g[c] = s;
}

// ---------------------------------------------------------------------------
// K8: units_out
// ---------------------------------------------------------------------------
__global__ void k_units(const float* __restrict__ W,
                        const float* __restrict__ bias,
                        float* __restrict__ out_units) {
    int u = blockIdx.x;
    int d = blockIdx.y * 256 + threadIdx.x;
    __shared__ float sin[N_C];
    for (int i = threadIdx.x; i < N_C; i += 256) sin[i] = g_unit_in[u * N_C + i];
    __syncthreads();
    const float* Wu = W + (size_t)u * N_C * N_C + d;
    float acc = 0.f;
    #pragma unroll 16
    for (int c = 0; c < N_C; c++) acc += sin[c] * Wu[(size_t)c * N_C];
    float h = acc + bias[u * N_C + d];
    out_units[u * N_C + d] = sin[d] + (h > 0.f ? h : 0.f);
}

// ---------------------------------------------------------------------------
extern "C" void kernel_launch(void* const* d_in, const int* in_sizes, int n_in,
                              void* d_out, int out_size) {
    const float* state       = (const float*)d_in[0];
    const float* input_tails = (const float*)d_in[1];
    const float* exit_heads  = (const float*)d_in[2];
    const float* unit_heads  = (const float*)d_in[3];
    const float* unit_W      = (const float*)d_in[5];
    const float* unit_b      = (const float*)d_in[6];

    float* out       = (float*)d_out;
    float* out_exit  = out;
    float* out_garb  = out + N_O * N_C;
    float* out_units = out + N_O * N_C + N_C;

    cudaFuncSetAttribute(k_dist_mma,
                         cudaFuncAttributeMaxDynamicSharedMemorySize,
                         SMEM_DIST);

    k_prep1<<<N_Q + N_I / 4, 128>>>(unit_heads, exit_heads, input_tails);  // 0
    k_sims<<<dim3(N_Q / BM, N_I / BN), 256>>>(input_tails);                // 1
    k_prep2<<<8192 + (N_QP - N_Q), 256>>>(state);                          // 2
    k_dist_mma<<<dim3(N_QP / 64, N_C / 64, KSPLIT), 256, SMEM_DIST>>>();   // 3 <- profiled
    k_colsum_part<<<dim3(N_I / 256, 8), 256>>>();                          // 4
    k_wfinal<<<N_I / 256, 256>>>();                                        // 5
    k_dist_red<<<N_Q, 256>>>(out_exit);                                    // 6
    k_gpart<<<256, 256>>>(state);                                          // 7
    k_greduce<<<N_C / 256, 256>>>(out_garb);                               // 8
    k_units<<<dim3(N_U, N_C / 256), 256>>>(unit_W, unit_b, out_units);     // 9
}

// round 10
// speedup vs baseline: 3.3997x; 2.2114x over previous
#include <cuda_runtime.h>
#include <cuda_bf16.h>
#include <cuda_fp16.h>
#include <cstdint>

// ---------------------------------------------------------------------------
// ManifoldWorms pipeline, round 9: all-tensor-core GEMMs, streamed units
//   output flat f32: exit_outputs(512x1024) | garbage(1024) | units_out(64x1024)
// ---------------------------------------------------------------------------

#define N_Q   576
#define N_QP  640
#define N_I   8192
#define N_E   128
#define N_C   1024
#define N_U   64
#define N_O   512
#define KSPLIT 8

// ------------------------- device scratch ----------------------------------
__device__ float   g_tinv[N_I];
__device__ __half  g_Qhi[N_QP * N_E];     // normalized queries hi (pad rows stay 0)
__device__ __half  g_Qlo[N_QP * N_E];     // normalized queries lo
__device__ __half  g_Thi[N_I * N_E];      // raw tails hi
__device__ __half  g_Tlo[N_I * N_E];      // raw tails lo
__device__ __half  g_A [N_QP * N_I];      // influences fp16
__device__ __half  g_B1[N_C * N_I];       // state^T hi fp16
__device__ __half  g_B2[N_C * N_I];       // state^T lo fp16
__device__ float   g_cs[8 * N_I];
__device__ float   g_w[N_I];
__device__ float   g_unit_in[N_U * N_C];
__device__ float   g_gpart[256 * N_C];
__device__ float   g_part[KSPLIT * N_QP * N_C];   // 21 MB GEMM partials
__device__ float   g_upart[8][N_U][N_C];          // 2 MB unit partials

// ------------------------- helpers -----------------------------------------
__device__ __forceinline__ uint32_t smem_u32(const void* p) {
    uint32_t a;
    asm("{ .reg .u64 t; cvta.to.shared.u64 t, %1; cvt.u32.u64 %0, t; }"
        : "=r"(a) : "l"(p));
    return a;
}
__device__ __forceinline__ void cp16(uint32_t dst, const void* src) {
    asm volatile("cp.async.cg.shared.global [%0], [%1], 16;\n"
                 :: "r"(dst), "l"(src) : "memory");
}
#define CP_COMMIT() asm volatile("cp.async.commit_group;\n" ::: "memory")
#define CP_WAIT(n)  asm volatile("cp.async.wait_group %0;\n" :: "n"(n) : "memory")

__device__ __forceinline__ void ldm_x4(uint32_t* r, uint32_t addr) {
    asm volatile("ldmatrix.sync.aligned.m8n8.x4.shared.b16 {%0,%1,%2,%3}, [%4];"
        : "=r"(r[0]), "=r"(r[1]), "=r"(r[2]), "=r"(r[3]) : "r"(addr));
}
__device__ __forceinline__ void mma_f16(float* c, const uint32_t* a,
                                        uint32_t b0, uint32_t b1) {
    asm volatile(
        "mma.sync.aligned.m16n8k16.row.col.f32.f16.f16.f32 "
        "{%0,%1,%2,%3}, {%4,%5,%6,%7}, {%8,%9}, {%0,%1,%2,%3};\n"
        : "+f"(c[0]), "+f"(c[1]), "+f"(c[2]), "+f"(c[3])
        : "r"(a[0]), "r"(a[1]), "r"(a[2]), "r"(a[3]), "r"(b0), "r"(b1));
}

// ---------------------------------------------------------------------------
// K0 (prep1): queries -> normalized fp16 hi/lo;  tails -> tinv + fp16 hi/lo
// ---------------------------------------------------------------------------
__global__ void k_prep1(const float* __restrict__ unit_heads,
                        const float* __restrict__ exit_heads,
                        const float* __restrict__ tails) {
    if (blockIdx.x < N_Q) {
        int row = blockIdx.x;
        const float* src = (row < N_U) ? (unit_heads + row * N_E)
                                       : (exit_heads + (row - N_U) * N_E);
        float v = src[threadIdx.x];
        float s = v * v;
        #pragma unroll
        for (int o = 16; o; o >>= 1) s += __shfl_xor_sync(0xffffffffu, s, o);
        __shared__ float ws[4];
        if ((threadIdx.x & 31) == 0) ws[threadIdx.x >> 5] = s;
        __syncthreads();
        float q = v * rsqrtf(ws[0] + ws[1] + ws[2] + ws[3]);
        __half h = __float2half(q);
        g_Qhi[row * N_E + threadIdx.x] = h;
        g_Qlo[row * N_E + threadIdx.x] = __float2half(q - __half2float(h));
    } else {
        int warp = threadIdx.x >> 5, lane = threadIdx.x & 31;
        int row = (blockIdx.x - N_Q) * 4 + warp;
        const float* r = tails + row * N_E;
        float vv[4];
        float s = 0.f;
        #pragma unroll
        for (int i = 0; i < 4; i++) { vv[i] = r[lane + 32 * i]; s += vv[i] * vv[i]; }
        #pragma unroll
        for (int o = 16; o; o >>= 1) s += __shfl_xor_sync(0xffffffffu, s, o);
        if (lane == 0) g_tinv[row] = rsqrtf(s);
        #pragma unroll
        for (int i = 0; i < 4; i++) {
            __half h = __float2half(vv[i]);
            g_Thi[row * N_E + lane + 32 * i] = h;
            g_Tlo[row * N_E + lane + 32 * i] = __float2half(vv[i] - __half2float(h));
        }
    }
}

// ---------------------------------------------------------------------------
// K1 (sims): influences = relu((Qn @ T^T) * tinv)  via 3-product fp16 mma
//     CTA tile M=64 N=128, K=128 in 2 chunks of 64; 8 warps (2x4), 32x32 tiles
// ---------------------------------------------------------------------------
#define SIMS_QB   9216                    // 64 rows * 144 B
#define SIMS_TB   18432                   // 128 rows * 144 B
#define SIMS_THI  (2 * SIMS_QB)
#define SIMS_TLO  (2 * SIMS_QB + SIMS_TB)
#define SMEM_SIMS (2 * SIMS_QB + 2 * SIMS_TB)   // 55296

__global__ void __launch_bounds__(256, 2)
k_sims_mma() {
    extern __shared__ uint16_t sh[];
    uint32_t sbase = smem_u32(sh);
    int tid  = threadIdx.x;
    int wid  = tid >> 5, lane = tid & 31;
    int wm   = wid & 1, wn = wid >> 1;        // 2 x 4 warp grid
    int g    = lane >> 2, c = lane & 3;
    int l15  = lane & 15;
    int lhalf = (lane >> 4) << 4;

    int q0 = blockIdx.x * 64;
    int j0 = blockIdx.y * 128;

    const char* Qh = (const char*)g_Qhi;
    const char* Ql = (const char*)g_Qlo;
    const char* Th = (const char*)g_Thi;
    const char* Tl = (const char*)g_Tlo;

    float acc[2][4][4] = {};

    for (int ch = 0; ch < 2; ch++) {
        int k0 = ch * 64;
        #pragma unroll
        for (int i = 0; i < 2; i++) {
            int u = tid + i * 256;
            int row = u >> 3, seg = u & 7;
            uint32_t d = sbase + row * 144 + seg * 16;
            long off = ((long)(q0 + row) * N_E + k0 + seg * 8) << 1;
            cp16(d, Qh + off);
            cp16(d + SIMS_QB, Ql + off);
        }
        #pragma unroll
        for (int i = 0; i < 4; i++) {
            int u = tid + i * 256;
            int row = u >> 3, seg = u & 7;
            uint32_t d = sbase + SIMS_THI + row * 144 + seg * 16;
            long off = ((long)(j0 + row) * N_E + k0 + seg * 8) << 1;
            cp16(d, Th + off);
            cp16(d + SIMS_TB, Tl + off);
        }
        CP_COMMIT();
        CP_WAIT(0);
        __syncthreads();

        uint32_t aRow0 = sbase + (wm * 32 + l15) * 144 + lhalf;
        uint32_t aRow1 = aRow0 + 16 * 144;
        uint32_t bRow0 = sbase + SIMS_THI + (wn * 32 + l15) * 144 + lhalf;
        uint32_t bRow1 = bRow0 + 16 * 144;

        #pragma unroll
        for (int kk = 0; kk < 4; kk++) {
            int cb = kk * 32;
            uint32_t ah[2][4], al[2][4], bhA[4], bhB[4], blA[4], blB[4];
            ldm_x4(ah[0], aRow0 + cb);
            ldm_x4(ah[1], aRow1 + cb);
            ldm_x4(al[0], aRow0 + SIMS_QB + cb);
            ldm_x4(al[1], aRow1 + SIMS_QB + cb);
            ldm_x4(bhA, bRow0 + cb);
            ldm_x4(bhB, bRow1 + cb);
            ldm_x4(blA, bRow0 + SIMS_TB + cb);
            ldm_x4(blB, bRow1 + SIMS_TB + cb);
            #pragma unroll
            for (int mi = 0; mi < 2; mi++) {
                // Qhi * Thi
                mma_f16(acc[mi][0], ah[mi], bhA[0], bhA[2]);
                mma_f16(acc[mi][1], ah[mi], bhA[1], bhA[3]);
                mma_f16(acc[mi][2], ah[mi], bhB[0], bhB[2]);
                mma_f16(acc[mi][3], ah[mi], bhB[1], bhB[3]);
                // Qhi * Tlo
                mma_f16(acc[mi][0], ah[mi], blA[0], blA[2]);
                mma_f16(acc[mi][1], ah[mi], blA[1], blA[3]);
                mma_f16(acc[mi][2], ah[mi], blB[0], blB[2]);
                mma_f16(acc[mi][3], ah[mi], blB[1], blB[3]);
                // Qlo * Thi
                mma_f16(acc[mi][0], al[mi], bhA[0], bhA[2]);
                mma_f16(acc[mi][1], al[mi], bhA[1], bhA[3]);
                mma_f16(acc[mi][2], al[mi], bhB[0], bhB[2]);
                mma_f16(acc[mi][3], al[mi], bhB[1], bhB[3]);
            }
        }
        __syncthreads();
    }

    #pragma unroll
    for (int mi = 0; mi < 2; mi++) {
        int m = q0 + wm * 32 + mi * 16 + g;
        #pragma unroll
        for (int ni = 0; ni < 4; ni++) {
            int j = j0 + wn * 32 + ni * 8 + 2 * c;
            float t0 = g_tinv[j], t1 = g_tinv[j + 1];
            float v0 = acc[mi][ni][0] * t0; v0 = v0 > 0.f ? v0 : 0.f;
            float v1 = acc[mi][ni][1] * t1; v1 = v1 > 0.f ? v1 : 0.f;
            float v2 = acc[mi][ni][2] * t0; v2 = v2 > 0.f ? v2 : 0.f;
            float v3 = acc[mi][ni][3] * t1; v3 = v3 > 0.f ? v3 : 0.f;
            *(__half2*)(g_A + (size_t)m * N_I + j)       = __floats2half2_rn(v0, v1);
            *(__half2*)(g_A + (size_t)(m + 8) * N_I + j) = __floats2half2_rn(v2, v3);
        }
    }
}

// ---------------------------------------------------------------------------
// K2 (prep2): state transpose+split -> B1/B2 [C][K] fp16
// ---------------------------------------------------------------------------
__global__ void k_prep2(const float* __restrict__ state) {
    __shared__ float t[32][33];
    int kb = blockIdx.x & 255;
    int cb = blockIdx.x >> 8;
    int k0 = kb * 32, c0 = cb * 32;
    int tx = threadIdx.x & 31, ty = threadIdx.x >> 5;
    #pragma unroll
    for (int i = 0; i < 4; i++)
        t[ty + 8 * i][tx] = state[(size_t)(k0 + ty + 8 * i) * N_C + c0 + tx];
    __syncthreads();
    #pragma unroll
    for (int i = 0; i < 4; i++) {
        int c = c0 + ty + 8 * i;
        int k = k0 + tx;
        float v = t[tx][ty + 8 * i];
        __half h1 = __float2half(v);
        g_B1[c * N_I + k] = h1;
        g_B2[c * N_I + k] = __float2half(v - __half2float(h1));
    }
}

// ---------------------------------------------------------------------------
// K3 (dist): distributed = influences @ state; fp16 2-product mma
//     CTA 128x64, 8 warps (4x2), warp tile 32x32, BK=64, double buffer
// ---------------------------------------------------------------------------
#define KC       64
#define DIST_AB  18432                 // 128 rows * 144 B
#define DIST_BB  9216                  // 64 rows * 144 B
#define STAGEB   (DIST_AB + 2 * DIST_BB)   // 36864
#define SMEM_DIST (2 * STAGEB)             // 73728

__global__ void __launch_bounds__(256, 2)
k_dist_mma() {
    extern __shared__ uint16_t sh[];
    uint32_t sbase = smem_u32(sh);

    int tid  = threadIdx.x;
    int wid  = tid >> 5, lane = tid & 31;
    int wm   = wid >> 1, wn = wid & 1;        // 4 x 2 warp grid
    int g    = lane >> 2, c = lane & 3;
    int l15  = lane & 15;
    int lhalf = (lane >> 4) << 4;

    int q0 = blockIdx.x * 128;
    int c0 = blockIdx.y * 64;
    int ks = blockIdx.z;
    int kbase = ks * (N_I / KSPLIT);

    const char* Aa = (const char*)g_A;
    const char* B1 = (const char*)g_B1;
    const char* B2 = (const char*)g_B2;

    float acc[2][4][4] = {};
    const int NCHUNK = (N_I / KSPLIT) / KC;   // 16

    auto load_chunk = [&](int it) {
        int k0 = kbase + it * KC;
        uint32_t buf = sbase + (it & 1) * STAGEB;
        #pragma unroll
        for (int i = 0; i < 4; i++) {
            int u   = tid + i * 256;
            int row = u >> 3, seg = u & 7;
            long aoff = ((long)(q0 + row) * N_I + k0 + seg * 8) << 1;
            cp16(buf + row * 144 + seg * 16, Aa + aoff);
        }
        #pragma unroll
        for (int i = 0; i < 2; i++) {
            int u   = tid + i * 256;
            int row = u >> 3, seg = u & 7;
            uint32_t d = buf + DIST_AB + row * 144 + seg * 16;
            long boff = ((long)(c0 + row) * N_I + k0 + seg * 8) << 1;
            cp16(d,           B1 + boff);
            cp16(d + DIST_BB, B2 + boff);
        }
    };

    load_chunk(0);
    CP_COMMIT();

    for (int it = 0; it < NCHUNK; it++) {
        if (it + 1 < NCHUNK) { load_chunk(it + 1); CP_COMMIT(); CP_WAIT(1); }
        else                 { CP_WAIT(0); }
        __syncthreads();

        uint32_t buf = sbase + (it & 1) * STAGEB;
        uint32_t aRow0 = buf + (wm * 32 + l15) * 144 + lhalf;
        uint32_t aRow1 = aRow0 + 16 * 144;
        uint32_t bRow0 = buf + DIST_AB + (wn * 32 + l15) * 144 + lhalf;
        uint32_t bRow1 = bRow0 + 16 * 144;

        #pragma unroll
        for (int kk = 0; kk < 4; kk++) {
            int cb = kk * 32;
            uint32_t a[2][4], b1A[4], b1B[4], b2A[4], b2B[4];
            ldm_x4(a[0], aRow0 + cb);
            ldm_x4(a[1], aRow1 + cb);
            ldm_x4(b1A, bRow0 + cb);
            ldm_x4(b1B, bRow1 + cb);
            ldm_x4(b2A, bRow0 + DIST_BB + cb);
            ldm_x4(b2B, bRow1 + DIST_BB + cb);
            #pragma unroll
            for (int mi = 0; mi < 2; mi++) {
                mma_f16(acc[mi][0], a[mi], b1A[0], b1A[2]);
                mma_f16(acc[mi][1], a[mi], b1A[1], b1A[3]);
                mma_f16(acc[mi][2], a[mi], b1B[0], b1B[2]);
                mma_f16(acc[mi][3], a[mi], b1B[1], b1B[3]);
                mma_f16(acc[mi][0], a[mi], b2A[0], b2A[2]);
                mma_f16(acc[mi][1], a[mi], b2A[1], b2A[3]);
                mma_f16(acc[mi][2], a[mi], b2B[0], b2B[2]);
                mma_f16(acc[mi][3], a[mi], b2B[1], b2B[3]);
            }
        }
        __syncthreads();
    }

    float* part = g_part + (size_t)ks * N_QP * N_C;
    #pragma unroll
    for (int mi = 0; mi < 2; mi++) {
        int m0 = q0 + wm * 32 + mi * 16 + g;
        #pragma unroll
        for (int ni = 0; ni < 4; ni++) {
            int n0 = c0 + wn * 32 + ni * 8 + 2 * c;
            part[(size_t)m0 * N_C + n0]           = acc[mi][ni][0];
            part[(size_t)m0 * N_C + n0 + 1]       = acc[mi][ni][1];
            part[(size_t)(m0 + 8) * N_C + n0]     = acc[mi][ni][2];
            part[(size_t)(m0 + 8) * N_C + n0 + 1] = acc[mi][ni][3];
        }
    }
}

// ---------------------------------------------------------------------------
// K4/K5: colsum partials over q chunks, then w
// ---------------------------------------------------------------------------
__global__ void k_colsum_part() {
    int j = blockIdx.x * 256 + threadIdx.x;
    int qc = blockIdx.y;
    float s = 0.f;
    for (int q = qc * 72; q < (qc + 1) * 72; q++)
        s += __half2float(g_A[(size_t)q * N_I + j]);
    g_cs[qc * N_I + j] = s;
}
__global__ void k_wfinal() {
    int j = blockIdx.x * 256 + threadIdx.x;
    float s = 0.f;
    #pragma unroll
    for (int p = 0; p < 8; p++) s += g_cs[p * N_I + j];
    g_w[j] = 1.0f - s;
}

// ---------------------------------------------------------------------------
// K6: reduce K-split partials and route to outputs
// ---------------------------------------------------------------------------
__global__ void k_dist_red(float* __restrict__ out_exit) {
    int m = blockIdx.x;
    for (int n = threadIdx.x; n < N_C; n += 256) {
        float s = 0.f;
        #pragma unroll
        for (int ks = 0; ks < KSPLIT; ks++)
            s += g_part[((size_t)ks * N_QP + m) * N_C + n];
        if (m < N_U) g_unit_in[m * N_C + n] = s;
        else         out_exit[(size_t)(m - N_U) * N_C + n] = s;
    }
}

// ---------------------------------------------------------------------------
// K7: garbage = sum_j w[j]*state[j][:]
// ---------------------------------------------------------------------------
__global__ void k_gpart(const float* __restrict__ state) {
    int jc = blockIdx.x;
    int tid = threadIdx.x;
    float acc[4] = {};
    for (int r = 0; r < 32; r++) {
        int j = jc * 32 + r;
        float wj = g_w[j];
        const float* row = state + (size_t)j * N_C;
        #pragma unroll
        for (int i = 0; i < 4; i++) acc[i] += wj * row[tid + 256 * i];
    }
    #pragma unroll
    for (int i = 0; i < 4; i++) g_gpart[jc * N_C + tid + 256 * i] = acc[i];
}
__global__ void k_greduce(float* __restrict__ out_g) {
    int c = blockIdx.x * 256 + threadIdx.x;
    float s = 0.f;
    for (int p = 0; p < 256; p++) s += g_gpart[p * N_C + c];
    out_g[c] = s;
}

// ---------------------------------------------------------------------------
// K8: units, two-phase.  part: grid (64 u, 8 c-slices), contiguous 512KB/blk
// ---------------------------------------------------------------------------
__global__ void __launch_bounds__(256) k_units_part(const float* __restrict__ W) {
    int u = blockIdx.x, sl = blockIdx.y;
    int c0 = sl * 128;
    __shared__ float sin[128];
    if (threadIdx.x < 128) sin[threadIdx.x] = g_unit_in[u * N_C + c0 + threadIdx.x];
    __syncthreads();
    const float4* Wu = (const float4*)(W + ((size_t)u * N_C + c0) * N_C) + threadIdx.x;
    float4 acc = make_float4(0.f, 0.f, 0.f, 0.f);
    #pragma unroll 4
    for (int c = 0; c < 128; c++) {
        float4 w4 = Wu[(size_t)c * (N_C / 4)];
        float s = sin[c];
        acc.x += s * w4.x; acc.y += s * w4.y;
        acc.z += s * w4.z; acc.w += s * w4.w;
    }
    ((float4*)&g_upart[sl][u][0])[threadIdx.x] = acc;
}

__global__ void k_units_fin(const float* __restrict__ bias,
                            float* __restrict__ out_units) {
    int u = blockIdx.x;
    int d4 = threadIdx.x;
    float4 s = make_float4(0.f, 0.f, 0.f, 0.f);
    #pragma unroll
    for (int sl = 0; sl < 8; sl++) {
        float4 p = ((const float4*)&g_upart[sl][u][0])[d4];
        s.x += p.x; s.y += p.y; s.z += p.z; s.w += p.w;
    }
    float4 b4 = ((const float4*)(bias + u * N_C))[d4];
    float4 in4 = ((const float4*)(g_unit_in + u * N_C))[d4];
    float hx = s.x + b4.x, hy = s.y + b4.y, hz = s.z + b4.z, hw = s.w + b4.w;
    float4 o;
    o.x = in4.x + (hx > 0.f ? hx : 0.f);
    o.y = in4.y + (hy > 0.f ? hy : 0.f);
    o.z = in4.z + (hz > 0.f ? hz : 0.f);
    o.w = in4.w + (hw > 0.f ? hw : 0.f);
    ((float4*)(out_units + u * N_C))[d4] = o;
}

// ---------------------------------------------------------------------------
extern "C" void kernel_launch(void* const* d_in, const int* in_sizes, int n_in,
                              void* d_out, int out_size) {
    const float* state       = (const float*)d_in[0];
    const float* input_tails = (const float*)d_in[1];
    const float* exit_heads  = (const float*)d_in[2];
    const float* unit_heads  = (const float*)d_in[3];
    const float* unit_W      = (const float*)d_in[5];
    const float* unit_b      = (const float*)d_in[6];

    float* out       = (float*)d_out;
    float* out_exit  = out;
    float* out_garb  = out + N_O * N_C;
    float* out_units = out + N_O * N_C + N_C;

    cudaFuncSetAttribute(k_dist_mma,
                         cudaFuncAttributeMaxDynamicSharedMemorySize, SMEM_DIST);
    cudaFuncSetAttribute(k_sims_mma,
                         cudaFuncAttributeMaxDynamicSharedMemorySize, SMEM_SIMS);

    k_prep1<<<N_Q + N_I / 4, 128>>>(unit_heads, exit_heads, input_tails);      // 0
    k_sims_mma<<<dim3(N_QP / 64, N_I / 128), 256, SMEM_SIMS>>>();              // 1
    k_prep2<<<8192, 256>>>(state);                                             // 2
    k_dist_mma<<<dim3(N_QP / 128, N_C / 64, KSPLIT), 256, SMEM_DIST>>>();      // 3 <- profiled
    k_colsum_part<<<dim3(N_I / 256, 8), 256>>>();                              // 4
    k_wfinal<<<N_I / 256, 256>>>();                                            // 5
    k_dist_red<<<N_Q, 256>>>(out_exit);                                        // 6
    k_gpart<<<256, 256>>>(state);                                              // 7
    k_greduce<<<N_C / 256, 256>>>(out_garb);                                   // 8
    k_units_part<<<dim3(N_U, 8), 256>>>(unit_W);                               // 9
    k_units_fin<<<N_U, 256>>>(unit_b, out_units);                              // 10
}

// round 11
// speedup vs baseline: 4.1120x; 1.2095x over previous
#include <cuda_runtime.h>
#include <cuda_bf16.h>
#include <cuda_fp16.h>
#include <cstdint>

// ---------------------------------------------------------------------------
// ManifoldWorms pipeline, round 10: single-product fp16 dist GEMM (HMMA /2),
// 9 launches.  Output: exit_outputs(512x1024) | garbage(1024) | units(64x1024)
// ---------------------------------------------------------------------------

#define N_Q   576
#define N_QP  640
#define N_I   8192
#define N_E   128
#define N_C   1024
#define N_U   64
#define N_O   512
#define KSPLIT 8

// ------------------------- device scratch ----------------------------------
__device__ float   g_tinv[N_I];
__device__ __half  g_Qhi[N_QP * N_E];     // normalized queries hi (pad rows stay 0)
__device__ __half  g_Qlo[N_QP * N_E];     // normalized queries lo
__device__ __half  g_Thi[N_I * N_E];      // raw tails hi
__device__ __half  g_Tlo[N_I * N_E];      // raw tails lo
__device__ __half  g_A [N_QP * N_I];      // influences fp16
__device__ __half  g_B1[N_C * N_I];       // state^T fp16 (single)
__device__ float   g_cs[8 * N_I];
__device__ float   g_unit_in[N_U * N_C];
__device__ float   g_gpart[256 * N_C];
__device__ float   g_part[KSPLIT * N_QP * N_C];   // 21 MB GEMM partials
__device__ float   g_upart[8][N_U][N_C];          // 2 MB unit partials

// ------------------------- helpers -----------------------------------------
__device__ __forceinline__ uint32_t smem_u32(const void* p) {
    uint32_t a;
    asm("{ .reg .u64 t; cvta.to.shared.u64 t, %1; cvt.u32.u64 %0, t; }"
        : "=r"(a) : "l"(p));
    return a;
}
__device__ __forceinline__ void cp16(uint32_t dst, const void* src) {
    asm volatile("cp.async.cg.shared.global [%0], [%1], 16;\n"
                 :: "r"(dst), "l"(src) : "memory");
}
#define CP_COMMIT() asm volatile("cp.async.commit_group;\n" ::: "memory")
#define CP_WAIT(n)  asm volatile("cp.async.wait_group %0;\n" :: "n"(n) : "memory")

__device__ __forceinline__ void ldm_x4(uint32_t* r, uint32_t addr) {
    asm volatile("ldmatrix.sync.aligned.m8n8.x4.shared.b16 {%0,%1,%2,%3}, [%4];"
        : "=r"(r[0]), "=r"(r[1]), "=r"(r[2]), "=r"(r[3]) : "r"(addr));
}
__device__ __forceinline__ void mma_f16(float* c, const uint32_t* a,
                                        uint32_t b0, uint32_t b1) {
    asm volatile(
        "mma.sync.aligned.m16n8k16.row.col.f32.f16.f16.f32 "
        "{%0,%1,%2,%3}, {%4,%5,%6,%7}, {%8,%9}, {%0,%1,%2,%3};\n"
        : "+f"(c[0]), "+f"(c[1]), "+f"(c[2]), "+f"(c[3])
        : "r"(a[0]), "r"(a[1]), "r"(a[2]), "r"(a[3]), "r"(b0), "r"(b1));
}

// ---------------------------------------------------------------------------
// K0 (prep1): queries -> normalized fp16 hi/lo;  tails -> tinv + fp16 hi/lo
// ---------------------------------------------------------------------------
__global__ void k_prep1(const float* __restrict__ unit_heads,
                        const float* __restrict__ exit_heads,
                        const float* __restrict__ tails) {
    if (blockIdx.x < N_Q) {
        int row = blockIdx.x;
        const float* src = (row < N_U) ? (unit_heads + row * N_E)
                                       : (exit_heads + (row - N_U) * N_E);
        float v = src[threadIdx.x];
        float s = v * v;
        #pragma unroll
        for (int o = 16; o; o >>= 1) s += __shfl_xor_sync(0xffffffffu, s, o);
        __shared__ float ws[4];
        if ((threadIdx.x & 31) == 0) ws[threadIdx.x >> 5] = s;
        __syncthreads();
        float q = v * rsqrtf(ws[0] + ws[1] + ws[2] + ws[3]);
        __half h = __float2half(q);
        g_Qhi[row * N_E + threadIdx.x] = h;
        g_Qlo[row * N_E + threadIdx.x] = __float2half(q - __half2float(h));
    } else {
        int warp = threadIdx.x >> 5, lane = threadIdx.x & 31;
        int row = (blockIdx.x - N_Q) * 4 + warp;
        const float* r = tails + row * N_E;
        float vv[4];
        float s = 0.f;
        #pragma unroll
        for (int i = 0; i < 4; i++) { vv[i] = r[lane + 32 * i]; s += vv[i] * vv[i]; }
        #pragma unroll
        for (int o = 16; o; o >>= 1) s += __shfl_xor_sync(0xffffffffu, s, o);
        if (lane == 0) g_tinv[row] = rsqrtf(s);
        #pragma unroll
        for (int i = 0; i < 4; i++) {
            __half h = __float2half(vv[i]);
            g_Thi[row * N_E + lane + 32 * i] = h;
            g_Tlo[row * N_E + lane + 32 * i] = __float2half(vv[i] - __half2float(h));
        }
    }
}

// ---------------------------------------------------------------------------
// K1 (sims): influences = relu((Qn @ T^T) * tinv)  via 3-product fp16 mma
//     CTA tile M=64 N=128, K=128 in 2 chunks; 8 warps (2x4), 32x32 tiles
// ---------------------------------------------------------------------------
#define SIMS_QB   9216                    // 64 rows * 144 B
#define SIMS_TB   18432                   // 128 rows * 144 B
#define SIMS_THI  (2 * SIMS_QB)
#define SMEM_SIMS (2 * SIMS_QB + 2 * SIMS_TB)   // 55296

__global__ void __launch_bounds__(256, 2)
k_sims_mma() {
    extern __shared__ uint16_t sh[];
    uint32_t sbase = smem_u32(sh);
    int tid  = threadIdx.x;
    int wid  = tid >> 5, lane = tid & 31;
    int wm   = wid & 1, wn = wid >> 1;
    int g    = lane >> 2, c = lane & 3;
    int l15  = lane & 15;
    int lhalf = (lane >> 4) << 4;

    int q0 = blockIdx.x * 64;
    int j0 = blockIdx.y * 128;

    const char* Qh = (const char*)g_Qhi;
    const char* Ql = (const char*)g_Qlo;
    const char* Th = (const char*)g_Thi;
    const char* Tl = (const char*)g_Tlo;

    float acc[2][4][4] = {};

    for (int ch = 0; ch < 2; ch++) {
        int k0 = ch * 64;
        #pragma unroll
        for (int i = 0; i < 2; i++) {
            int u = tid + i * 256;
            int row = u >> 3, seg = u & 7;
            uint32_t d = sbase + row * 144 + seg * 16;
            long off = ((long)(q0 + row) * N_E + k0 + seg * 8) << 1;
            cp16(d, Qh + off);
            cp16(d + SIMS_QB, Ql + off);
        }
        #pragma unroll
        for (int i = 0; i < 4; i++) {
            int u = tid + i * 256;
            int row = u >> 3, seg = u & 7;
            uint32_t d = sbase + SIMS_THI + row * 144 + seg * 16;
            long off = ((long)(j0 + row) * N_E + k0 + seg * 8) << 1;
            cp16(d, Th + off);
            cp16(d + SIMS_TB, Tl + off);
        }
        CP_COMMIT();
        CP_WAIT(0);
        __syncthreads();

        uint32_t aRow0 = sbase + (wm * 32 + l15) * 144 + lhalf;
        uint32_t aRow1 = aRow0 + 16 * 144;
        uint32_t bRow0 = sbase + SIMS_THI + (wn * 32 + l15) * 144 + lhalf;
        uint32_t bRow1 = bRow0 + 16 * 144;

        #pragma unroll
        for (int kk = 0; kk < 4; kk++) {
            int cb = kk * 32;
            uint32_t ah[2][4], al[2][4], bhA[4], bhB[4], blA[4], blB[4];
            ldm_x4(ah[0], aRow0 + cb);
            ldm_x4(ah[1], aRow1 + cb);
            ldm_x4(al[0], aRow0 + SIMS_QB + cb);
            ldm_x4(al[1], aRow1 + SIMS_QB + cb);
            ldm_x4(bhA, bRow0 + cb);
            ldm_x4(bhB, bRow1 + cb);
            ldm_x4(blA, bRow0 + SIMS_TB + cb);
            ldm_x4(blB, bRow1 + SIMS_TB + cb);
            #pragma unroll
            for (int mi = 0; mi < 2; mi++) {
                mma_f16(acc[mi][0], ah[mi], bhA[0], bhA[2]);
                mma_f16(acc[mi][1], ah[mi], bhA[1], bhA[3]);
                mma_f16(acc[mi][2], ah[mi], bhB[0], bhB[2]);
                mma_f16(acc[mi][3], ah[mi], bhB[1], bhB[3]);
                mma_f16(acc[mi][0], ah[mi], blA[0], blA[2]);
                mma_f16(acc[mi][1], ah[mi], blA[1], blA[3]);
                mma_f16(acc[mi][2], ah[mi], blB[0], blB[2]);
                mma_f16(acc[mi][3], ah[mi], blB[1], blB[3]);
                mma_f16(acc[mi][0], al[mi], bhA[0], bhA[2]);
                mma_f16(acc[mi][1], al[mi], bhA[1], bhA[3]);
                mma_f16(acc[mi][2], al[mi], bhB[0], bhB[2]);
                mma_f16(acc[mi][3], al[mi], bhB[1], bhB[3]);
            }
        }
        __syncthreads();
    }

    #pragma unroll
    for (int mi = 0; mi < 2; mi++) {
        int m = q0 + wm * 32 + mi * 16 + g;
        #pragma unroll
        for (int ni = 0; ni < 4; ni++) {
            int j = j0 + wn * 32 + ni * 8 + 2 * c;
            float t0 = g_tinv[j], t1 = g_tinv[j + 1];
            float v0 = acc[mi][ni][0] * t0; v0 = v0 > 0.f ? v0 : 0.f;
            float v1 = acc[mi][ni][1] * t1; v1 = v1 > 0.f ? v1 : 0.f;
            float v2 = acc[mi][ni][2] * t0; v2 = v2 > 0.f ? v2 : 0.f;
            float v3 = acc[mi][ni][3] * t1; v3 = v3 > 0.f ? v3 : 0.f;
            *(__half2*)(g_A + (size_t)m * N_I + j)       = __floats2half2_rn(v0, v1);
            *(__half2*)(g_A + (size_t)(m + 8) * N_I + j) = __floats2half2_rn(v2, v3);
        }
    }
}

// ---------------------------------------------------------------------------
// K2 (prep2): state transpose -> B1 [C][K] fp16 (single precision product)
// ---------------------------------------------------------------------------
__global__ void k_prep2(const float* __restrict__ state) {
    __shared__ float t[32][33];
    int kb = blockIdx.x & 255;
    int cb = blockIdx.x >> 8;
    int k0 = kb * 32, c0 = cb * 32;
    int tx = threadIdx.x & 31, ty = threadIdx.x >> 5;
    #pragma unroll
    for (int i = 0; i < 4; i++)
        t[ty + 8 * i][tx] = state[(size_t)(k0 + ty + 8 * i) * N_C + c0 + tx];
    __syncthreads();
    #pragma unroll
    for (int i = 0; i < 4; i++) {
        int c = c0 + ty + 8 * i;
        int k = k0 + tx;
        g_B1[c * N_I + k] = __float2half(t[tx][ty + 8 * i]);
    }
}

// ---------------------------------------------------------------------------
// K3 (dist): distributed = influences @ state; single-product fp16 mma
//     CTA 128x64, 8 warps (4x2), warp tile 32x32, BK=64, double buffer
// ---------------------------------------------------------------------------
#define KC       64
#define DIST_AB  18432                 // 128 rows * 144 B
#define DIST_BB  9216                  // 64 rows * 144 B
#define STAGEB   (DIST_AB + DIST_BB)       // 27648
#define SMEM_DIST (2 * STAGEB)             // 55296

__global__ void __launch_bounds__(256, 2)
k_dist_mma() {
    extern __shared__ uint16_t sh[];
    uint32_t sbase = smem_u32(sh);

    int tid  = threadIdx.x;
    int wid  = tid >> 5, lane = tid & 31;
    int wm   = wid >> 1, wn = wid & 1;
    int g    = lane >> 2, c = lane & 3;
    int l15  = lane & 15;
    int lhalf = (lane >> 4) << 4;

    int q0 = blockIdx.x * 128;
    int c0 = blockIdx.y * 64;
    int ks = blockIdx.z;
    int kbase = ks * (N_I / KSPLIT);

    const char* Aa = (const char*)g_A;
    const char* B1 = (const char*)g_B1;

    float acc[2][4][4] = {};
    const int NCHUNK = (N_I / KSPLIT) / KC;   // 16

    auto load_chunk = [&](int it) {
        int k0 = kbase + it * KC;
        uint32_t buf = sbase + (it & 1) * STAGEB;
        #pragma unroll
        for (int i = 0; i < 4; i++) {
            int u   = tid + i * 256;
            int row = u >> 3, seg = u & 7;
            long aoff = ((long)(q0 + row) * N_I + k0 + seg * 8) << 1;
            cp16(buf + row * 144 + seg * 16, Aa + aoff);
        }
        #pragma unroll
        for (int i = 0; i < 2; i++) {
            int u   = tid + i * 256;
            int row = u >> 3, seg = u & 7;
            long boff = ((long)(c0 + row) * N_I + k0 + seg * 8) << 1;
            cp16(buf + DIST_AB + row * 144 + seg * 16, B1 + boff);
        }
    };

    load_chunk(0);
    CP_COMMIT();

    for (int it = 0; it < NCHUNK; it++) {
        if (it + 1 < NCHUNK) { load_chunk(it + 1); CP_COMMIT(); CP_WAIT(1); }
        else                 { CP_WAIT(0); }
        __syncthreads();

        uint32_t buf = sbase + (it & 1) * STAGEB;
        uint32_t aRow0 = buf + (wm * 32 + l15) * 144 + lhalf;
        uint32_t aRow1 = aRow0 + 16 * 144;
        uint32_t bRow0 = buf + DIST_AB + (wn * 32 + l15) * 144 + lhalf;
        uint32_t bRow1 = bRow0 + 16 * 144;

        #pragma unroll
        for (int kk = 0; kk < 4; kk++) {
            int cb = kk * 32;
            uint32_t a[2][4], bA[4], bB[4];
            ldm_x4(a[0], aRow0 + cb);
            ldm_x4(a[1], aRow1 + cb);
            ldm_x4(bA, bRow0 + cb);
            ldm_x4(bB, bRow1 + cb);
            #pragma unroll
            for (int mi = 0; mi < 2; mi++) {
                mma_f16(acc[mi][0], a[mi], bA[0], bA[2]);
                mma_f16(acc[mi][1], a[mi], bA[1], bA[3]);
                mma_f16(acc[mi][2], a[mi], bB[0], bB[2]);
                mma_f16(acc[mi][3], a[mi], bB[1], bB[3]);
            }
        }
        __syncthreads();
    }

    float* part = g_part + (size_t)ks * N_QP * N_C;
    #pragma unroll
    for (int mi = 0; mi < 2; mi++) {
        int m0 = q0 + wm * 32 + mi * 16 + g;
        #pragma unroll
        for (int ni = 0; ni < 4; ni++) {
            int n0 = c0 + wn * 32 + ni * 8 + 2 * c;
            part[(size_t)m0 * N_C + n0]           = acc[mi][ni][0];
            part[(size_t)m0 * N_C + n0 + 1]       = acc[mi][ni][1];
            part[(size_t)(m0 + 8) * N_C + n0]     = acc[mi][ni][2];
            part[(size_t)(m0 + 8) * N_C + n0 + 1] = acc[mi][ni][3];
        }
    }
}

// ---------------------------------------------------------------------------
// K4: colsum partials over q chunks
// ---------------------------------------------------------------------------
__global__ void k_colsum_part() {
    int j = blockIdx.x * 256 + threadIdx.x;
    int qc = blockIdx.y;
    float s = 0.f;
    for (int q = qc * 72; q < (qc + 1) * 72; q++)
        s += __half2float(g_A[(size_t)q * N_I + j]);
    g_cs[qc * N_I + j] = s;
}

// ---------------------------------------------------------------------------
// K5: reduce K-split partials and route to outputs
// ---------------------------------------------------------------------------
__global__ void k_dist_red(float* __restrict__ out_exit) {
    int m = blockIdx.x;
    for (int n = threadIdx.x; n < N_C; n += 256) {
        float s = 0.f;
        #pragma unroll
        for (int ks = 0; ks < KSPLIT; ks++)
            s += g_part[((size_t)ks * N_QP + m) * N_C + n];
        if (m < N_U) g_unit_in[m * N_C + n] = s;
        else         out_exit[(size_t)(m - N_U) * N_C + n] = s;
    }
}

// ---------------------------------------------------------------------------
// K6: garbage partials; w computed inline from g_cs
// ---------------------------------------------------------------------------
__global__ void k_gpart_w(const float* __restrict__ state) {
    int jc = blockIdx.x;               // 256 chunks of 32 rows
    int tid = threadIdx.x;
    __shared__ float ws[32];
    if (tid < 32) {
        int j = jc * 32 + tid;
        float s = 0.f;
        #pragma unroll
        for (int p = 0; p < 8; p++) s += g_cs[p * N_I + j];
        ws[tid] = 1.0f - s;
    }
    __syncthreads();
    float acc[4] = {};
    for (int r = 0; r < 32; r++) {
        float wj = ws[r];
        const float* row = state + (size_t)(jc * 32 + r) * N_C;
        #pragma unroll
        for (int i = 0; i < 4; i++) acc[i] += wj * row[tid + 256 * i];
    }
    #pragma unroll
    for (int i = 0; i < 4; i++) g_gpart[jc * N_C + tid + 256 * i] = acc[i];
}

// ---------------------------------------------------------------------------
// K7: units partials: grid (64 u, 8 c-slices), contiguous 512KB/blk stream
// ---------------------------------------------------------------------------
__global__ void __launch_bounds__(256) k_units_part(const float* __restrict__ W) {
    int u = blockIdx.x, sl = blockIdx.y;
    int c0 = sl * 128;
    __shared__ float sin[128];
    if (threadIdx.x < 128) sin[threadIdx.x] = g_unit_in[u * N_C + c0 + threadIdx.x];
    __syncthreads();
    const float4* Wu = (const float4*)(W + ((size_t)u * N_C + c0) * N_C) + threadIdx.x;
    float4 acc = make_float4(0.f, 0.f, 0.f, 0.f);
    #pragma unroll 4
    for (int c = 0; c < 128; c++) {
        float4 w4 = Wu[(size_t)c * (N_C / 4)];
        float s = sin[c];
        acc.x += s * w4.x; acc.y += s * w4.y;
        acc.z += s * w4.z; acc.w += s * w4.w;
    }
    ((float4*)&g_upart[sl][u][0])[threadIdx.x] = acc;
}

// ---------------------------------------------------------------------------
// K8: units finalize (blocks 0..63) + garbage reduce (blocks 64..67)
// ---------------------------------------------------------------------------
__global__ void k_fin(const float* __restrict__ bias,
                      float* __restrict__ out_units,
                      float* __restrict__ out_g) {
    if (blockIdx.x < N_U) {
        int u = blockIdx.x;
        int d4 = threadIdx.x;
        float4 s = make_float4(0.f, 0.f, 0.f, 0.f);
        #pragma unroll
        for (int sl = 0; sl < 8; sl++) {
            float4 p = ((const float4*)&g_upart[sl][u][0])[d4];
            s.x += p.x; s.y += p.y; s.z += p.z; s.w += p.w;
        }
        float4 b4 = ((const float4*)(bias + u * N_C))[d4];
        float4 in4 = ((const float4*)(g_unit_in + u * N_C))[d4];
        float hx = s.x + b4.x, hy = s.y + b4.y, hz = s.z + b4.z, hw = s.w + b4.w;
        float4 o;
        o.x = in4.x + (hx > 0.f ? hx : 0.f);
        o.y = in4.y + (hy > 0.f ? hy : 0.f);
        o.z = in4.z + (hz > 0.f ? hz : 0.f);
        o.w = in4.w + (hw > 0.f ? hw : 0.f);
        ((float4*)(out_units + u * N_C))[d4] = o;
    } else {
        int c = (blockIdx.x - N_U) * 256 + threadIdx.x;
        float s = 0.f;
        for (int p = 0; p < 256; p++) s += g_gpart[p * N_C + c];
        out_g[c] = s;
    }
}

// ---------------------------------------------------------------------------
extern "C" void kernel_launch(void* const* d_in, const int* in_sizes, int n_in,
                              void* d_out, int out_size) {
    const float* state       = (const float*)d_in[0];
    const float* input_tails = (const float*)d_in[1];
    const float* exit_heads  = (const float*)d_in[2];
    const float* unit_heads  = (const float*)d_in[3];
    const float* unit_W      = (const float*)d_in[5];
    const float* unit_b      = (const float*)d_in[6];

    float* out       = (float*)d_out;
    float* out_exit  = out;
    float* out_garb  = out + N_O * N_C;
    float* out_units = out + N_O * N_C + N_C;

    cudaFuncSetAttribute(k_dist_mma,
                         cudaFuncAttributeMaxDynamicSharedMemorySize, SMEM_DIST);
    cudaFuncSetAttribute(k_sims_mma,
                         cudaFuncAttributeMaxDynamicSharedMemorySize, SMEM_SIMS);

    k_prep1<<<N_Q + N_I / 4, 128>>>(unit_heads, exit_heads, input_tails);      // 0
    k_sims_mma<<<dim3(N_QP / 64, N_I / 128), 256, SMEM_SIMS>>>();              // 1
    k_prep2<<<8192, 256>>>(state);                                             // 2
    k_dist_mma<<<dim3(N_QP / 128, N_C / 64, KSPLIT), 256, SMEM_DIST>>>();      // 3 <- profiled
    k_colsum_part<<<dim3(N_I / 256, 8), 256>>>();                              // 4
    k_dist_red<<<N_Q, 256>>>(out_exit);                                        // 5
    k_gpart_w<<<256, 256>>>(state);                                            // 6
    k_units_part<<<dim3(N_U, 8), 256>>>(unit_W);                               // 7
    k_fin<<<N_U + N_C / 256, 256>>>(unit_b, out_units, out_garb);              // 8
}

// round 12
// speedup vs baseline: 4.1291x; 1.0042x over previous
#include <cuda_runtime.h>
#include <cuda_bf16.h>
#include <cuda_fp16.h>
#include <cstdint>

// ---------------------------------------------------------------------------
// ManifoldWorms pipeline, round 11: stream-overlapped DAG
//   prep2 || (prep1+sims);  colsum/gpart || dist;  units_part || distB
//   Output flat f32: exit_outputs(512x1024) | garbage(1024) | units(64x1024)
// ---------------------------------------------------------------------------

#define N_Q   576
#define N_QP  640
#define N_I   8192
#define N_E   128
#define N_C   1024
#define N_U   64
#define N_O   512

// ------------------------- device scratch ----------------------------------
__device__ float   g_tinv[N_I];
__device__ __half  g_Qhi[N_QP * N_E];
__device__ __half  g_Qlo[N_QP * N_E];
__device__ __half  g_Thi[N_I * N_E];
__device__ __half  g_Tlo[N_I * N_E];
__device__ __half  g_A [N_QP * N_I];
__device__ __half  g_B1[N_C * N_I];
__device__ float   g_cs[8 * N_I];
__device__ float   g_unit_in[N_U * N_C];
__device__ float   g_gpart[256 * N_C];
__device__ float   g_partA[16 * 128 * N_C];   // 8 MB  (q-tile 0, KSPLIT 16)
__device__ float   g_partB[8 * 512 * N_C];    // 16 MB (q-tiles 1..4, KSPLIT 8)
__device__ float   g_upart[8][N_U][N_C];

// ------------------------- helpers -----------------------------------------
__device__ __forceinline__ uint32_t smem_u32(const void* p) {
    uint32_t a;
    asm("{ .reg .u64 t; cvta.to.shared.u64 t, %1; cvt.u32.u64 %0, t; }"
        : "=r"(a) : "l"(p));
    return a;
}
__device__ __forceinline__ void cp16(uint32_t dst, const void* src) {
    asm volatile("cp.async.cg.shared.global [%0], [%1], 16;\n"
                 :: "r"(dst), "l"(src) : "memory");
}
#define CP_COMMIT() asm volatile("cp.async.commit_group;\n" ::: "memory")
#define CP_WAIT(n)  asm volatile("cp.async.wait_group %0;\n" :: "n"(n) : "memory")

__device__ __forceinline__ void ldm_x4(uint32_t* r, uint32_t addr) {
    asm volatile("ldmatrix.sync.aligned.m8n8.x4.shared.b16 {%0,%1,%2,%3}, [%4];"
        : "=r"(r[0]), "=r"(r[1]), "=r"(r[2]), "=r"(r[3]) : "r"(addr));
}
__device__ __forceinline__ void mma_f16(float* c, const uint32_t* a,
                                        uint32_t b0, uint32_t b1) {
    asm volatile(
        "mma.sync.aligned.m16n8k16.row.col.f32.f16.f16.f32 "
        "{%0,%1,%2,%3}, {%4,%5,%6,%7}, {%8,%9}, {%0,%1,%2,%3};\n"
        : "+f"(c[0]), "+f"(c[1]), "+f"(c[2]), "+f"(c[3])
        : "r"(a[0]), "r"(a[1]), "r"(a[2]), "r"(a[3]), "r"(b0), "r"(b1));
}

// ---------------------------------------------------------------------------
// K0 (prep1): queries -> normalized fp16 hi/lo;  tails -> tinv + fp16 hi/lo
// ---------------------------------------------------------------------------
__global__ void k_prep1(const float* __restrict__ unit_heads,
                        const float* __restrict__ exit_heads,
                        const float* __restrict__ tails) {
    if (blockIdx.x < N_Q) {
        int row = blockIdx.x;
        const float* src = (row < N_U) ? (unit_heads + row * N_E)
                                       : (exit_heads + (row - N_U) * N_E);
        float v = src[threadIdx.x];
        float s = v * v;
        #pragma unroll
        for (int o = 16; o; o >>= 1) s += __shfl_xor_sync(0xffffffffu, s, o);
        __shared__ float ws[4];
        if ((threadIdx.x & 31) == 0) ws[threadIdx.x >> 5] = s;
        __syncthreads();
        float q = v * rsqrtf(ws[0] + ws[1] + ws[2] + ws[3]);
        __half h = __float2half(q);
        g_Qhi[row * N_E + threadIdx.x] = h;
        g_Qlo[row * N_E + threadIdx.x] = __float2half(q - __half2float(h));
    } else {
        int warp = threadIdx.x >> 5, lane = threadIdx.x & 31;
        int row = (blockIdx.x - N_Q) * 4 + warp;
        const float* r = tails + row * N_E;
        float vv[4];
        float s = 0.f;
        #pragma unroll
        for (int i = 0; i < 4; i++) { vv[i] = r[lane + 32 * i]; s += vv[i] * vv[i]; }
        #pragma unroll
        for (int o = 16; o; o >>= 1) s += __shfl_xor_sync(0xffffffffu, s, o);
        if (lane == 0) g_tinv[row] = rsqrtf(s);
        #pragma unroll
        for (int i = 0; i < 4; i++) {
            __half h = __float2half(vv[i]);
            g_Thi[row * N_E + lane + 32 * i] = h;
            g_Tlo[row * N_E + lane + 32 * i] = __float2half(vv[i] - __half2float(h));
        }
    }
}

// ---------------------------------------------------------------------------
// K1 (sims): influences = relu((Qn @ T^T) * tinv)  via 3-product fp16 mma
// ---------------------------------------------------------------------------
#define SIMS_QB   9216
#define SIMS_TB   18432
#define SIMS_THI  (2 * SIMS_QB)
#define SMEM_SIMS (2 * SIMS_QB + 2 * SIMS_TB)   // 55296

__global__ void __launch_bounds__(256, 2)
k_sims_mma() {
    extern __shared__ uint16_t sh[];
    uint32_t sbase = smem_u32(sh);
    int tid  = threadIdx.x;
    int wid  = tid >> 5, lane = tid & 31;
    int wm   = wid & 1, wn = wid >> 1;
    int g    = lane >> 2, c = lane & 3;
    int l15  = lane & 15;
    int lhalf = (lane >> 4) << 4;

    int q0 = blockIdx.x * 64;
    int j0 = blockIdx.y * 128;

    const char* Qh = (const char*)g_Qhi;
    const char* Ql = (const char*)g_Qlo;
    const char* Th = (const char*)g_Thi;
    const char* Tl = (const char*)g_Tlo;

    float acc[2][4][4] = {};

    for (int ch = 0; ch < 2; ch++) {
        int k0 = ch * 64;
        #pragma unroll
        for (int i = 0; i < 2; i++) {
            int u = tid + i * 256;
            int row = u >> 3, seg = u & 7;
            uint32_t d = sbase + row * 144 + seg * 16;
            long off = ((long)(q0 + row) * N_E + k0 + seg * 8) << 1;
            cp16(d, Qh + off);
            cp16(d + SIMS_QB, Ql + off);
        }
        #pragma unroll
        for (int i = 0; i < 4; i++) {
            int u = tid + i * 256;
            int row = u >> 3, seg = u & 7;
            uint32_t d = sbase + SIMS_THI + row * 144 + seg * 16;
            long off = ((long)(j0 + row) * N_E + k0 + seg * 8) << 1;
            cp16(d, Th + off);
            cp16(d + SIMS_TB, Tl + off);
        }
        CP_COMMIT();
        CP_WAIT(0);
        __syncthreads();

        uint32_t aRow0 = sbase + (wm * 32 + l15) * 144 + lhalf;
        uint32_t aRow1 = aRow0 + 16 * 144;
        uint32_t bRow0 = sbase + SIMS_THI + (wn * 32 + l15) * 144 + lhalf;
        uint32_t bRow1 = bRow0 + 16 * 144;

        #pragma unroll
        for (int kk = 0; kk < 4; kk++) {
            int cb = kk * 32;
            uint32_t ah[2][4], al[2][4], bhA[4], bhB[4], blA[4], blB[4];
            ldm_x4(ah[0], aRow0 + cb);
            ldm_x4(ah[1], aRow1 + cb);
            ldm_x4(al[0], aRow0 + SIMS_QB + cb);
            ldm_x4(al[1], aRow1 + SIMS_QB + cb);
            ldm_x4(bhA, bRow0 + cb);
            ldm_x4(bhB, bRow1 + cb);
            ldm_x4(blA, bRow0 + SIMS_TB + cb);
            ldm_x4(blB, bRow1 + SIMS_TB + cb);
            #pragma unroll
            for (int mi = 0; mi < 2; mi++) {
                mma_f16(acc[mi][0], ah[mi], bhA[0], bhA[2]);
                mma_f16(acc[mi][1], ah[mi], bhA[1], bhA[3]);
                mma_f16(acc[mi][2], ah[mi], bhB[0], bhB[2]);
                mma_f16(acc[mi][3], ah[mi], bhB[1], bhB[3]);
                mma_f16(acc[mi][0], ah[mi], blA[0], blA[2]);
                mma_f16(acc[mi][1], ah[mi], blA[1], blA[3]);
                mma_f16(acc[mi][2], ah[mi], blB[0], blB[2]);
                mma_f16(acc[mi][3], ah[mi], blB[1], blB[3]);
                mma_f16(acc[mi][0], al[mi], bhA[0], bhA[2]);
                mma_f16(acc[mi][1], al[mi], bhA[1], bhA[3]);
                mma_f16(acc[mi][2], al[mi], bhB[0], bhB[2]);
                mma_f16(acc[mi][3], al[mi], bhB[1], bhB[3]);
            }
        }
        __syncthreads();
    }

    #pragma unroll
    for (int mi = 0; mi < 2; mi++) {
        int m = q0 + wm * 32 + mi * 16 + g;
        #pragma unroll
        for (int ni = 0; ni < 4; ni++) {
            int j = j0 + wn * 32 + ni * 8 + 2 * c;
            float t0 = g_tinv[j], t1 = g_tinv[j + 1];
            float v0 = acc[mi][ni][0] * t0; v0 = v0 > 0.f ? v0 : 0.f;
            float v1 = acc[mi][ni][1] * t1; v1 = v1 > 0.f ? v1 : 0.f;
            float v2 = acc[mi][ni][2] * t0; v2 = v2 > 0.f ? v2 : 0.f;
            float v3 = acc[mi][ni][3] * t1; v3 = v3 > 0.f ? v3 : 0.f;
            *(__half2*)(g_A + (size_t)m * N_I + j)       = __floats2half2_rn(v0, v1);
            *(__half2*)(g_A + (size_t)(m + 8) * N_I + j) = __floats2half2_rn(v2, v3);
        }
    }
}

// ---------------------------------------------------------------------------
// K2 (prep2): state transpose -> B1 [C][K] fp16
// ---------------------------------------------------------------------------
__global__ void k_prep2(const float* __restrict__ state) {
    __shared__ float t[32][33];
    int kb = blockIdx.x & 255;
    int cb = blockIdx.x >> 8;
    int k0 = kb * 32, c0 = cb * 32;
    int tx = threadIdx.x & 31, ty = threadIdx.x >> 5;
    #pragma unroll
    for (int i = 0; i < 4; i++)
        t[ty + 8 * i][tx] = state[(size_t)(k0 + ty + 8 * i) * N_C + c0 + tx];
    __syncthreads();
    #pragma unroll
    for (int i = 0; i < 4; i++) {
        int c = c0 + ty + 8 * i;
        int k = k0 + tx;
        g_B1[c * N_I + k] = __float2half(t[tx][ty + 8 * i]);
    }
}

// ---------------------------------------------------------------------------
// K3 (dist): distributed = influences @ state; single-product fp16 mma
//     CTA 128x64, split into distA (q-tile 0, Z=16) and distB (tiles 1-4, Z=8)
// ---------------------------------------------------------------------------
#define KC       64
#define DIST_AB  18432
#define DIST_BB  9216
#define STAGEB   (DIST_AB + DIST_BB)       // 27648
#define SMEM_DIST (2 * STAGEB)             // 55296

__global__ void __launch_bounds__(256, 2)
k_dist_mma(int q_tile_off, int use_b) {
    extern __shared__ uint16_t sh[];
    uint32_t sbase = smem_u32(sh);

    int tid  = threadIdx.x;
    int wid  = tid >> 5, lane = tid & 31;
    int wm   = wid >> 1, wn = wid & 1;
    int g    = lane >> 2, c = lane & 3;
    int l15  = lane & 15;
    int lhalf = (lane >> 4) << 4;

    int q0 = (blockIdx.x + q_tile_off) * 128;
    int c0 = blockIdx.y * 64;
    int kspan = N_I / gridDim.z;
    int kbase = blockIdx.z * kspan;
    int NCHUNK = kspan / KC;

    const char* Aa = (const char*)g_A;
    const char* B1 = (const char*)g_B1;

    float acc[2][4][4] = {};

    auto load_chunk = [&](int it) {
        int k0 = kbase + it * KC;
        uint32_t buf = sbase + (it & 1) * STAGEB;
        #pragma unroll
        for (int i = 0; i < 4; i++) {
            int u   = tid + i * 256;
            int row = u >> 3, seg = u & 7;
            long aoff = ((long)(q0 + row) * N_I + k0 + seg * 8) << 1;
            cp16(buf + row * 144 + seg * 16, Aa + aoff);
        }
        #pragma unroll
        for (int i = 0; i < 2; i++) {
            int u   = tid + i * 256;
            int row = u >> 3, seg = u & 7;
            long boff = ((long)(c0 + row) * N_I + k0 + seg * 8) << 1;
            cp16(buf + DIST_AB + row * 144 + seg * 16, B1 + boff);
        }
    };

    load_chunk(0);
    CP_COMMIT();

    for (int it = 0; it < NCHUNK; it++) {
        if (it + 1 < NCHUNK) { load_chunk(it + 1); CP_COMMIT(); CP_WAIT(1); }
        else                 { CP_WAIT(0); }
        __syncthreads();

        uint32_t buf = sbase + (it & 1) * STAGEB;
        uint32_t aRow0 = buf + (wm * 32 + l15) * 144 + lhalf;
        uint32_t aRow1 = aRow0 + 16 * 144;
        uint32_t bRow0 = buf + DIST_AB + (wn * 32 + l15) * 144 + lhalf;
        uint32_t bRow1 = bRow0 + 16 * 144;

        #pragma unroll
        for (int kk = 0; kk < 4; kk++) {
            int cb = kk * 32;
            uint32_t a[2][4], bA[4], bB[4];
            ldm_x4(a[0], aRow0 + cb);
            ldm_x4(a[1], aRow1 + cb);
            ldm_x4(bA, bRow0 + cb);
            ldm_x4(bB, bRow1 + cb);
            #pragma unroll
            for (int mi = 0; mi < 2; mi++) {
                mma_f16(acc[mi][0], a[mi], bA[0], bA[2]);
                mma_f16(acc[mi][1], a[mi], bA[1], bA[3]);
                mma_f16(acc[mi][2], a[mi], bB[0], bB[2]);
                mma_f16(acc[mi][3], a[mi], bB[1], bB[3]);
            }
        }
        __syncthreads();
    }

    float* part = (use_b ? g_partB : g_partA)
                + (size_t)blockIdx.z * gridDim.x * 128 * N_C;
    #pragma unroll
    for (int mi = 0; mi < 2; mi++) {
        int m0 = blockIdx.x * 128 + wm * 32 + mi * 16 + g;   // local row
        #pragma unroll
        for (int ni = 0; ni < 4; ni++) {
            int n0 = c0 + wn * 32 + ni * 8 + 2 * c;
            part[(size_t)m0 * N_C + n0]           = acc[mi][ni][0];
            part[(size_t)m0 * N_C + n0 + 1]       = acc[mi][ni][1];
            part[(size_t)(m0 + 8) * N_C + n0]     = acc[mi][ni][2];
            part[(size_t)(m0 + 8) * N_C + n0 + 1] = acc[mi][ni][3];
        }
    }
}

// ---------------------------------------------------------------------------
// K4: colsum partials over q chunks
// ---------------------------------------------------------------------------
__global__ void k_colsum_part() {
    int j = blockIdx.x * 256 + threadIdx.x;
    int qc = blockIdx.y;
    float s = 0.f;
    for (int q = qc * 72; q < (qc + 1) * 72; q++)
        s += __half2float(g_A[(size_t)q * N_I + j]);
    g_cs[qc * N_I + j] = s;
}

// ---------------------------------------------------------------------------
// K5a: reduce distA partials for unit rows 0..63 -> g_unit_in
// ---------------------------------------------------------------------------
__global__ void k_redU() {
    int m = blockIdx.x;                 // 0..63
    for (int n = threadIdx.x; n < N_C; n += 256) {
        float s = 0.f;
        #pragma unroll
        for (int ks = 0; ks < 16; ks++)
            s += g_partA[((size_t)ks * 128 + m) * N_C + n];
        g_unit_in[m * N_C + n] = s;
    }
}

// K5b: reduce exit rows 64..575 -> out_exit
__global__ void k_redE(float* __restrict__ out_exit) {
    int m = blockIdx.x + N_U;           // 64..575
    for (int n = threadIdx.x; n < N_C; n += 256) {
        float s = 0.f;
        if (m < 128) {
            #pragma unroll
            for (int ks = 0; ks < 16; ks++)
                s += g_partA[((size_t)ks * 128 + m) * N_C + n];
        } else {
            int lm = m - 128;
            #pragma unroll
            for (int ks = 0; ks < 8; ks++)
                s += g_partB[((size_t)ks * 512 + lm) * N_C + n];
        }
        out_exit[(size_t)(m - N_U) * N_C + n] = s;
    }
}

// ---------------------------------------------------------------------------
// K6: garbage partials; w computed inline from g_cs
// ---------------------------------------------------------------------------
__global__ void k_gpart_w(const float* __restrict__ state) {
    int jc = blockIdx.x;
    int tid = threadIdx.x;
    __shared__ float ws[32];
    if (tid < 32) {
        int j = jc * 32 + tid;
        float s = 0.f;
        #pragma unroll
        for (int p = 0; p < 8; p++) s += g_cs[p * N_I + j];
        ws[tid] = 1.0f - s;
    }
    __syncthreads();
    float acc[4] = {};
    for (int r = 0; r < 32; r++) {
        float wj = ws[r];
        const float* row = state + (size_t)(jc * 32 + r) * N_C;
        #pragma unroll
        for (int i = 0; i < 4; i++) acc[i] += wj * row[tid + 256 * i];
    }
    #pragma unroll
    for (int i = 0; i < 4; i++) g_gpart[jc * N_C + tid + 256 * i] = acc[i];
}

// ---------------------------------------------------------------------------
// K7: units partials: grid (64 u, 8 c-slices), contiguous 512KB/blk stream
// ---------------------------------------------------------------------------
__global__ void __launch_bounds__(256) k_units_part(const float* __restrict__ W) {
    int u = blockIdx.x, sl = blockIdx.y;
    int c0 = sl * 128;
    __shared__ float sin[128];
    if (threadIdx.x < 128) sin[threadIdx.x] = g_unit_in[u * N_C + c0 + threadIdx.x];
    __syncthreads();
    const float4* Wu = (const float4*)(W + ((size_t)u * N_C + c0) * N_C) + threadIdx.x;
    float4 acc = make_float4(0.f, 0.f, 0.f, 0.f);
    #pragma unroll 4
    for (int c = 0; c < 128; c++) {
        float4 w4 = Wu[(size_t)c * (N_C / 4)];
        float s = sin[c];
        acc.x += s * w4.x; acc.y += s * w4.y;
        acc.z += s * w4.z; acc.w += s * w4.w;
    }
    ((float4*)&g_upart[sl][u][0])[threadIdx.x] = acc;
}

// ---------------------------------------------------------------------------
// K8: units finalize (blocks 0..63) + garbage reduce (blocks 64..67)
// ---------------------------------------------------------------------------
__global__ void k_fin(const float* __restrict__ bias,
                      float* __restrict__ out_units,
                      float* __restrict__ out_g) {
    if (blockIdx.x < N_U) {
        int u = blockIdx.x;
        int d4 = threadIdx.x;
        float4 s = make_float4(0.f, 0.f, 0.f, 0.f);
        #pragma unroll
        for (int sl = 0; sl < 8; sl++) {
            float4 p = ((const float4*)&g_upart[sl][u][0])[d4];
            s.x += p.x; s.y += p.y; s.z += p.z; s.w += p.w;
        }
        float4 b4 = ((const float4*)(bias + u * N_C))[d4];
        float4 in4 = ((const float4*)(g_unit_in + u * N_C))[d4];
        float hx = s.x + b4.x, hy = s.y + b4.y, hz = s.z + b4.z, hw = s.w + b4.w;
        float4 o;
        o.x = in4.x + (hx > 0.f ? hx : 0.f);
        o.y = in4.y + (hy > 0.f ? hy : 0.f);
        o.z = in4.z + (hz > 0.f ? hz : 0.f);
        o.w = in4.w + (hw > 0.f ? hw : 0.f);
        ((float4*)(out_units + u * N_C))[d4] = o;
    } else {
        int c = (blockIdx.x - N_U) * 256 + threadIdx.x;
        float s = 0.f;
        for (int p = 0; p < 256; p++) s += g_gpart[p * N_C + c];
        out_g[c] = s;
    }
}

// ---------------------------------------------------------------------------
extern "C" void kernel_launch(void* const* d_in, const int* in_sizes, int n_in,
                              void* d_out, int out_size) {
    const float* state       = (const float*)d_in[0];
    const float* input_tails = (const float*)d_in[1];
    const float* exit_heads  = (const float*)d_in[2];
    const float* unit_heads  = (const float*)d_in[3];
    const float* unit_W      = (const float*)d_in[5];
    const float* unit_b      = (const float*)d_in[6];

    float* out       = (float*)d_out;
    float* out_exit  = out;
    float* out_garb  = out + N_O * N_C;
    float* out_units = out + N_O * N_C + N_C;

    // host-side stream/event objects, created once (no device memory involved)
    static cudaStream_t s1 = nullptr, s2 = nullptr, s3 = nullptr;
    static cudaEvent_t evF = nullptr, evB1, evA, evRU, evU, evG;
    if (!s1) {
        cudaStreamCreateWithFlags(&s1, cudaStreamNonBlocking);
        cudaStreamCreateWithFlags(&s2, cudaStreamNonBlocking);
        cudaStreamCreateWithFlags(&s3, cudaStreamNonBlocking);
        cudaEventCreateWithFlags(&evF,  cudaEventDisableTiming);
        cudaEventCreateWithFlags(&evB1, cudaEventDisableTiming);
        cudaEventCreateWithFlags(&evA,  cudaEventDisableTiming);
        cudaEventCreateWithFlags(&evRU, cudaEventDisableTiming);
        cudaEventCreateWithFlags(&evU,  cudaEventDisableTiming);
        cudaEventCreateWithFlags(&evG,  cudaEventDisableTiming);
    }

    cudaFuncSetAttribute(k_dist_mma,
                         cudaFuncAttributeMaxDynamicSharedMemorySize, SMEM_DIST);
    cudaFuncSetAttribute(k_sims_mma,
                         cudaFuncAttributeMaxDynamicSharedMemorySize, SMEM_SIMS);

    // ---- fork s1: prep2 (depends only on state) ----
    cudaEventRecord(evF, 0);
    cudaStreamWaitEvent(s1, evF, 0);
    k_prep2<<<8192, 256, 0, s1>>>(state);
    cudaEventRecord(evB1, s1);

    // ---- main chain: prep1 -> sims ----
    k_prep1<<<N_Q + N_I / 4, 128>>>(unit_heads, exit_heads, input_tails);
    k_sims_mma<<<dim3(N_QP / 64, N_I / 128), 256, SMEM_SIMS>>>();
    cudaEventRecord(evA, 0);

    // ---- fork s2: colsum + garbage partials (need A + state only) ----
    cudaStreamWaitEvent(s2, evA, 0);
    k_colsum_part<<<dim3(N_I / 256, 8), 256, 0, s2>>>();
    k_gpart_w<<<256, 256, 0, s2>>>(state);
    cudaEventRecord(evG, s2);

    // ---- distA (q-tile 0 = unit rows + exits 0..63), then unit reduce ----
    cudaStreamWaitEvent(0, evB1, 0);
    k_dist_mma<<<dim3(1, 16, 16), 256, SMEM_DIST>>>(0, 0);
    k_redU<<<N_U, 256>>>();
    cudaEventRecord(evRU, 0);

    // ---- fork s3: units stream (HBM-bound) overlaps distB (L2-bound) ----
    cudaStreamWaitEvent(s3, evRU, 0);
    k_units_part<<<dim3(N_U, 8), 256, 0, s3>>>(unit_W);
    cudaEventRecord(evU, s3);

    // ---- distB (q-tiles 1..4) + exit reduce ----
    k_dist_mma<<<dim3(4, 16, 8), 256, SMEM_DIST>>>(1, 1);
    k_redE<<<N_Q - N_U, 256>>>(out_exit);

    // ---- join everything, finalize ----
    cudaStreamWaitEvent(0, evU, 0);
    cudaStreamWaitEvent(0, evG, 0);
    k_fin<<<N_U + N_C / 256, 256>>>(unit_b, out_units, out_garb);
}